// round 5
// baseline (speedup 1.0000x reference)
#include <cuda_runtime.h>
#include <math.h>

#define PB 8
#define PC 64
#define PH 256
#define PW 256
#define PKX 64
#define PKY 32
#define NROWS (PB*PC*PH)

// ---- scratch (device globals; no runtime allocation) ----
__device__ __align__(16) float  g_T[256*64];
__device__ __align__(16) float  g_cos[256];
__device__ __align__(16) float  g_sin[256];
__device__ __align__(16) float2 g_X1[PB*PC*PH*PKY];   // after fwd-W  [b,c,h,ky]
__device__ __align__(16) float2 g_XF[PB*PC*PKX*PKY];  // after fwd-H  [b,c,kx',ky]
__device__ __align__(16) float2 g_OF[PB*PC*PKX*PKY];  // after mix
__device__ __align__(16) float2 g_Y1[PB*PC*PKY*PH];   // after inv-H  [b,c,ky,h]
__device__ __align__(16) float  g_y[PB*PC*PH*PW];     // spectral conv out
__device__ __align__(16) float  g_z[PB*PC*PH*PW];     // MLP out
__device__ __align__(16) float  g_p1[PB*PC*2];
__device__ __align__(16) float  g_p2[PB*PH*2];
__device__ __align__(16) float  g_s1[PB*2];
__device__ __align__(16) float  g_s2[PB*2];
__device__ __align__(16) float  g_gb[PB*PC*2];

__device__ __forceinline__ float gelu_f(float v) {
    return 0.5f * v * (1.0f + erff(v * 0.7071067811865476f));
}

// ---- twiddle tables ----
__global__ void k_tab() {
    int j = threadIdx.x;
    double sd, cd;
    sincospi((double)j * (2.0 / 256.0), &sd, &cd);
    g_cos[j] = (float)cd;
    g_sin[j] = (float)sd;
    for (int ky = 0; ky < 32; ++ky) {
        int idx = (ky * j) & 255;
        double s2, c2;
        sincospi((double)idx * (2.0 / 256.0), &s2, &c2);
        g_T[j * 64 + 2 * ky]     = (float)c2;
        g_T[j * 64 + 2 * ky + 1] = (float)(-s2);
    }
}

// ---- FiLM gamma/beta ----
__global__ void k_film(const float* __restrict__ t,
                       const float* __restrict__ gw, const float* __restrict__ gb,
                       const float* __restrict__ bw, const float* __restrict__ bb) {
    int b = blockIdx.x, o = threadIdx.x;
    float g = gb[o], be = bb[o];
    for (int c = 0; c < PC; ++c) {
        float tv = t[b * PC + c];
        g  += gw[o * PC + c] * tv;
        be += bw[o * PC + c] * tv;
    }
    g_gb[(b * PC + o) * 2]     = g;
    g_gb[(b * PC + o) * 2 + 1] = be;
}

// ---- forward DFT along W, truncated to 32 modes ----
__global__ void k_fwdW(const float* __restrict__ x) {
    extern __shared__ char smraw[];
    float* sx = (float*)smraw;           // 32*256
    float* sT = sx + 32 * 256;           // 256*64
    int tid = threadIdx.x;

    const float4* gx = (const float4*)(x + (size_t)blockIdx.x * 32 * 256);
    float4* sx4 = (float4*)sx;
    for (int i = tid; i < 2048; i += 256) sx4[i] = gx[i];
    const float4* gT4 = (const float4*)g_T;
    float4* sT4 = (float4*)sT;
    for (int i = tid; i < 4096; i += 256) sT4[i] = gT4[i];
    __syncthreads();

    int i2 = tid >> 4, j2 = tid & 15;
    float acc[2][4];
#pragma unroll
    for (int r = 0; r < 2; ++r)
#pragma unroll
        for (int u = 0; u < 4; ++u) acc[r][u] = 0.0f;

    const float* row0 = sx + (i2 * 2) * 256;
    const float* row1 = row0 + 256;
#pragma unroll 4
    for (int k = 0; k < 256; ++k) {
        float a0 = row0[k];
        float a1 = row1[k];
        float4 bv = *(const float4*)&sT[k * 64 + j2 * 4];
        acc[0][0] += a0 * bv.x; acc[0][1] += a0 * bv.y; acc[0][2] += a0 * bv.z; acc[0][3] += a0 * bv.w;
        acc[1][0] += a1 * bv.x; acc[1][1] += a1 * bv.y; acc[1][2] += a1 * bv.z; acc[1][3] += a1 * bv.w;
    }
    float* go = (float*)g_X1 + (size_t)blockIdx.x * 32 * 64;
#pragma unroll
    for (int r = 0; r < 2; ++r)
        *(float4*)&go[(i2 * 2 + r) * 64 + j2 * 4] =
            make_float4(acc[r][0], acc[r][1], acc[r][2], acc[r][3]);
}

// ---- forward DFT along H (64 kept rows) ----
__global__ void k_fwdH() {
    extern __shared__ char smraw[];
    float2* sX = (float2*)smraw;          // 256*32 float2
    float*  sc = (float*)smraw + 16384;
    float*  ss = sc + 256;
    int tid = threadIdx.x, bc = blockIdx.x;

    const float4* src = (const float4*)(g_X1 + (size_t)bc * 8192);
    float4* dst = (float4*)sX;
    for (int i = tid; i < 4096; i += 256) dst[i] = src[i];
    sc[tid] = g_cos[tid];
    ss[tid] = g_sin[tid];
    __syncthreads();

    int kxp = tid >> 2, q = tid & 3, ky0 = q * 8;
    int kxm = kxp + ((kxp >= 32) ? 192 : 0);
    float ar[8], ai[8];
#pragma unroll
    for (int j = 0; j < 8; ++j) { ar[j] = 0.0f; ai[j] = 0.0f; }

    int idx = 0;
    for (int h = 0; h < 256; ++h) {
        float cv = sc[idx], sv = ss[idx];
        idx = (idx + kxm) & 255;
        const float2* row = &sX[h * 32 + ky0];
#pragma unroll
        for (int j = 0; j < 8; ++j) {
            float2 v = row[j];
            ar[j] += v.x * cv + v.y * sv;   // (xr+ixi)(c - i s)
            ai[j] += v.y * cv - v.x * sv;
        }
    }
    float2* out = g_XF + ((size_t)bc * PKX + kxp) * PKY + ky0;
#pragma unroll
    for (int j = 0; j < 8; ++j) out[j] = make_float2(ar[j], ai[j]);
}

// ---- per-mode complex channel mixing ----
__global__ void __launch_bounds__(1024, 1)
k_mix(const float* __restrict__ w1r, const float* __restrict__ w1i,
      const float* __restrict__ w2r, const float* __restrict__ w2i) {
    extern __shared__ char smraw[];
    float2* sXF = (float2*)smraw;   // [(b*64+i)*32+ky], 16384 float2
    int kxp = blockIdx.x >> 1, half = blockIdx.x & 1;
    int tid = threadIdx.x;

    for (int i = tid; i < 16384; i += 1024) {
        int b = i >> 11, rest = i & 2047, ii = rest >> 5, kk = rest & 31;
        sXF[i] = g_XF[(((size_t)b * PC + ii) * PKX + kxp) * PKY + kk];
    }
    __syncthreads();

    int o = half * 32 + (tid >> 5), ky = tid & 31;
    const float* wr; const float* wi; int kxl;
    if (kxp < 32) { wr = w1r; wi = w1i; kxl = kxp; }
    else          { wr = w2r; wi = w2i; kxl = kxp - 32; }

    float ar[8], ai[8];
#pragma unroll
    for (int b = 0; b < 8; ++b) { ar[b] = 0.0f; ai[b] = 0.0f; }

    for (int i = 0; i < 64; ++i) {
        size_t widx = (((size_t)i * PC + o) * 32 + kxl) * 32 + ky;
        float wrv = wr[widx], wiv = wi[widx];
#pragma unroll
        for (int b = 0; b < 8; ++b) {
            float2 v = sXF[(b * 64 + i) * 32 + ky];
            ar[b] += v.x * wrv - v.y * wiv;
            ai[b] += v.x * wiv + v.y * wrv;
        }
    }
#pragma unroll
    for (int b = 0; b < 8; ++b)
        g_OF[(((size_t)b * PC + o) * PKX + kxp) * PKY + ky] = make_float2(ar[b], ai[b]);
}

// ---- inverse DFT along H ----
__global__ void k_invH() {
    __shared__ float2 sOF[2048];
    __shared__ float sc[256], ss[256];
    int tid = threadIdx.x, bc = blockIdx.x;

    const float2* src = g_OF + (size_t)bc * 2048;
    for (int i = tid; i < 2048; i += 256) sOF[i] = src[i];
    sc[tid] = g_cos[tid];
    ss[tid] = g_sin[tid];
    __syncthreads();

    int h = tid;
    float ar[32], ai[32];
#pragma unroll
    for (int ky = 0; ky < 32; ++ky) { ar[ky] = 0.0f; ai[ky] = 0.0f; }

    for (int kxp = 0; kxp < 64; ++kxp) {
        int kxm = kxp + ((kxp >= 32) ? 192 : 0);
        int idx = (kxm * h) & 255;
        float cv = sc[idx], sv = ss[idx];
        const float2* row = &sOF[kxp * 32];
#pragma unroll
        for (int ky = 0; ky < 32; ++ky) {
            float2 v = row[ky];
            ar[ky] += v.x * cv - v.y * sv;   // (or+ioi)(c + i s)
            ai[ky] += v.x * sv + v.y * cv;
        }
    }
    float2* out = g_Y1 + (size_t)bc * 8192;
#pragma unroll
    for (int ky = 0; ky < 32; ++ky) out[ky * 256 + h] = make_float2(ar[ky], ai[ky]);
}

// ---- inverse rfft along W + GN1 partials ----
__global__ void k_invW() {
    extern __shared__ char smraw[];
    float2* sY = (float2*)smraw;          // [ky][h]
    float*  sc = (float*)smraw + 16384;
    float*  ss = sc + 256;
    __shared__ float rbuf[16];
    int tid = threadIdx.x, bc = blockIdx.x;

    const float4* src = (const float4*)(g_Y1 + (size_t)bc * 8192);
    float4* dst = (float4*)sY;
    for (int i = tid; i < 4096; i += 256) dst[i] = src[i];
    sc[tid] = g_cos[tid];
    ss[tid] = g_sin[tid];
    __syncthreads();

    int w = tid;
    const float inv = 1.0f / 65536.0f;
    float cw[31], sw[31];
#pragma unroll
    for (int ky = 1; ky < 32; ++ky) {
        int idx = (ky * w) & 255;
        cw[ky - 1] = 2.0f * inv * sc[idx];
        sw[ky - 1] = 2.0f * inv * ss[idx];
    }

    float s = 0.0f, s2 = 0.0f;
    float* yout = g_y + (size_t)bc * 65536;
    for (int h = 0; h < 256; ++h) {
        float acc = inv * sY[h].x;  // ky=0: real part only (irfft semantics)
#pragma unroll
        for (int ky = 1; ky < 32; ++ky) {
            float2 v = sY[ky * 256 + h];
            acc += v.x * cw[ky - 1] - v.y * sw[ky - 1];
        }
        yout[h * 256 + w] = acc;
        s += acc;
        s2 += acc * acc;
    }

    for (int off = 16; off > 0; off >>= 1) {
        s  += __shfl_down_sync(0xffffffffu, s,  off);
        s2 += __shfl_down_sync(0xffffffffu, s2, off);
    }
    int lane = tid & 31, wid = tid >> 5;
    if (lane == 0) { rbuf[wid] = s; rbuf[wid + 8] = s2; }
    __syncthreads();
    if (tid == 0) {
        float S = 0.0f, S2 = 0.0f;
        for (int i = 0; i < 8; ++i) { S += rbuf[i]; S2 += rbuf[i + 8]; }
        g_p1[bc * 2] = S;
        g_p1[bc * 2 + 1] = S2;
    }
}

__global__ void k_red1() {
    int b = blockIdx.x, lane = threadIdx.x;
    float s  = g_p1[(b * 64 + lane) * 2]     + g_p1[(b * 64 + lane + 32) * 2];
    float s2 = g_p1[(b * 64 + lane) * 2 + 1] + g_p1[(b * 64 + lane + 32) * 2 + 1];
    for (int off = 16; off > 0; off >>= 1) {
        s  += __shfl_down_sync(0xffffffffu, s,  off);
        s2 += __shfl_down_sync(0xffffffffu, s2, off);
    }
    if (lane == 0) {
        float mean = s * (1.0f / 4194304.0f);
        float var  = s2 * (1.0f / 4194304.0f) - mean * mean;
        g_s1[b * 2] = mean;
        g_s1[b * 2 + 1] = rsqrtf(var + 1e-5f);
    }
}

// ---- GN1 apply + residual + gelu + MLP + GN2 partials ----
__global__ void k_mlp(const float* __restrict__ x,
                      const float* __restrict__ nw, const float* __restrict__ nb,
                      const float* __restrict__ w1, const float* __restrict__ b1,
                      const float* __restrict__ w2, const float* __restrict__ b2) {
    extern __shared__ char smraw[];
    float* sy2  = (float*)smraw;        // [c][w]  64*256
    float* sh   = sy2 + 16384;          // [m][w]  32*256
    float* sw1  = sh + 8192;            // [c][m]
    float* sw2  = sw1 + 2048;           // [m][c]
    float* sb1  = sw2 + 2048;
    float* sb2v = sb1 + 32;
    float* snw  = sb2v + 64;
    float* snb  = snw + 64;
    __shared__ float rbuf[16];

    int tid = threadIdx.x;
    int b = blockIdx.x >> 8, h = blockIdx.x & 255;

    for (int i = tid; i < 2048; i += 256) {
        int c = i >> 5, m = i & 31;
        sw1[i] = w1[m * 64 + c];
        int m2 = i >> 6, c2 = i & 63;
        sw2[i] = w2[c2 * 32 + m2];
    }
    if (tid < 64) {
        sb2v[tid] = b2[tid];
        snw[tid] = nw[tid];
        snb[tid] = nb[tid];
        if (tid < 32) sb1[tid] = b1[tid];
    }
    float mean1 = g_s1[b * 2], rstd1 = g_s1[b * 2 + 1];
    __syncthreads();

    for (int i = tid; i < 16384; i += 256) {
        int c = i >> 8, wc = i & 255;
        size_t gid = (size_t)(b * 64 + c) * 65536 + (size_t)h * 256 + wc;
        float tv = (g_y[gid] - mean1) * rstd1 * snw[c] + snb[c] + x[gid];
        sy2[i] = gelu_f(tv);
    }
    __syncthreads();

    int wg = tid & 31;
    int wA = wg * 4, wB = wA + 128;

    {   // layer 1: 32x64 @ 64x256
        int tm = tid >> 5, m0 = tm * 4;
        float acc[4][8];
#pragma unroll
        for (int mm = 0; mm < 4; ++mm)
#pragma unroll
            for (int ww = 0; ww < 8; ++ww) acc[mm][ww] = 0.0f;
        for (int c = 0; c < 64; ++c) {
            float4 wv = *(const float4*)&sw1[c * 32 + m0];
            float4 y0 = *(const float4*)&sy2[c * 256 + wA];
            float4 y1 = *(const float4*)&sy2[c * 256 + wB];
            float wa[4] = { wv.x, wv.y, wv.z, wv.w };
            float yv[8] = { y0.x, y0.y, y0.z, y0.w, y1.x, y1.y, y1.z, y1.w };
#pragma unroll
            for (int mm = 0; mm < 4; ++mm)
#pragma unroll
                for (int ww = 0; ww < 8; ++ww) acc[mm][ww] += wa[mm] * yv[ww];
        }
#pragma unroll
        for (int mm = 0; mm < 4; ++mm) {
            float bb = sb1[m0 + mm];
#pragma unroll
            for (int ww = 0; ww < 8; ++ww) {
                int wcol = (ww < 4) ? (wA + ww) : (wB + ww - 4);
                sh[(m0 + mm) * 256 + wcol] = gelu_f(acc[mm][ww] + bb);
            }
        }
    }
    __syncthreads();

    float s = 0.0f, s2 = 0.0f;
    {   // layer 2: 64x32 @ 32x256 + stats
        int tc = tid >> 5, c0 = tc * 8;
        float acc2[8][8];
#pragma unroll
        for (int cc = 0; cc < 8; ++cc)
#pragma unroll
            for (int ww = 0; ww < 8; ++ww) acc2[cc][ww] = 0.0f;
        for (int m = 0; m < 32; ++m) {
            float4 a0 = *(const float4*)&sw2[m * 64 + c0];
            float4 a1 = *(const float4*)&sw2[m * 64 + c0 + 4];
            float4 h0 = *(const float4*)&sh[m * 256 + wA];
            float4 h1 = *(const float4*)&sh[m * 256 + wB];
            float wa[8] = { a0.x, a0.y, a0.z, a0.w, a1.x, a1.y, a1.z, a1.w };
            float hv[8] = { h0.x, h0.y, h0.z, h0.w, h1.x, h1.y, h1.z, h1.w };
#pragma unroll
            for (int cc = 0; cc < 8; ++cc)
#pragma unroll
                for (int ww = 0; ww < 8; ++ww) acc2[cc][ww] += wa[cc] * hv[ww];
        }
#pragma unroll
        for (int cc = 0; cc < 8; ++cc) {
            float bb = sb2v[c0 + cc];
            float o[8];
#pragma unroll
            for (int ww = 0; ww < 8; ++ww) {
                o[ww] = acc2[cc][ww] + bb;
                s += o[ww];
                s2 += o[ww] * o[ww];
            }
            size_t gbase = (size_t)(b * 64 + c0 + cc) * 65536 + (size_t)h * 256;
            *(float4*)&g_z[gbase + wA] = make_float4(o[0], o[1], o[2], o[3]);
            *(float4*)&g_z[gbase + wB] = make_float4(o[4], o[5], o[6], o[7]);
        }
    }

    for (int off = 16; off > 0; off >>= 1) {
        s  += __shfl_down_sync(0xffffffffu, s,  off);
        s2 += __shfl_down_sync(0xffffffffu, s2, off);
    }
    int lane = tid & 31, widx = tid >> 5;
    if (lane == 0) { rbuf[widx] = s; rbuf[widx + 8] = s2; }
    __syncthreads();
    if (tid == 0) {
        float S = 0.0f, S2 = 0.0f;
        for (int i = 0; i < 8; ++i) { S += rbuf[i]; S2 += rbuf[i + 8]; }
        g_p2[blockIdx.x * 2] = S;
        g_p2[blockIdx.x * 2 + 1] = S2;
    }
}

__global__ void k_red2() {
    __shared__ float rbuf[16];
    int b = blockIdx.x, tid = threadIdx.x;
    float s  = g_p2[(b * 256 + tid) * 2];
    float s2 = g_p2[(b * 256 + tid) * 2 + 1];
    for (int off = 16; off > 0; off >>= 1) {
        s  += __shfl_down_sync(0xffffffffu, s,  off);
        s2 += __shfl_down_sync(0xffffffffu, s2, off);
    }
    int lane = tid & 31, wid = tid >> 5;
    if (lane == 0) { rbuf[wid] = s; rbuf[wid + 8] = s2; }
    __syncthreads();
    if (tid == 0) {
        float S = 0.0f, S2 = 0.0f;
        for (int i = 0; i < 8; ++i) { S += rbuf[i]; S2 += rbuf[i + 8]; }
        float mean = S * (1.0f / 4194304.0f);
        float var  = S2 * (1.0f / 4194304.0f) - mean * mean;
        g_s2[b * 2] = mean;
        g_s2[b * 2 + 1] = rsqrtf(var + 1e-5f);
    }
}

// ---- final: FiLM GN + skip2 ----
__global__ void k_final(const float* __restrict__ x, float* __restrict__ out) {
    int gi = blockIdx.x * 256 + threadIdx.x;
#pragma unroll
    for (int u = 0; u < 4; ++u) {
        size_t i4 = (size_t)gi + (size_t)u * 2097152;
        size_t e = i4 * 4;
        int b = (int)(e >> 22);
        int c = (int)((e >> 16) & 63);
        float mean = g_s2[b * 2], rstd = g_s2[b * 2 + 1];
        float ga = g_gb[(b * 64 + c) * 2], be = g_gb[(b * 64 + c) * 2 + 1];
        float4 zv = ((const float4*)g_z)[i4];
        float4 xv = ((const float4*)x)[i4];
        float4 ov;
        ov.x = ga * (zv.x - mean) * rstd + be + gelu_f(xv.x);
        ov.y = ga * (zv.y - mean) * rstd + be + gelu_f(xv.y);
        ov.z = ga * (zv.z - mean) * rstd + be + gelu_f(xv.z);
        ov.w = ga * (zv.w - mean) * rstd + be + gelu_f(xv.w);
        ((float4*)out)[i4] = ov;
    }
}

extern "C" void kernel_launch(void* const* d_in, const int* in_sizes, int n_in,
                              void* d_out, int out_size) {
    const float* x       = (const float*)d_in[0];
    const float* t       = (const float*)d_in[1];
    const float* w1r     = (const float*)d_in[2];
    const float* w1i     = (const float*)d_in[3];
    const float* w2r     = (const float*)d_in[4];
    const float* w2i     = (const float*)d_in[5];
    const float* norm1_w = (const float*)d_in[6];
    const float* norm1_b = (const float*)d_in[7];
    const float* mlp_w1  = (const float*)d_in[8];
    const float* mlp_b1  = (const float*)d_in[9];
    const float* mlp_w2  = (const float*)d_in[10];
    const float* mlp_b2  = (const float*)d_in[11];
    const float* gamma_w = (const float*)d_in[12];
    const float* gamma_b = (const float*)d_in[13];
    const float* beta_w  = (const float*)d_in[14];
    const float* beta_b  = (const float*)d_in[15];
    float* out = (float*)d_out;

    cudaFuncSetAttribute(k_fwdW, cudaFuncAttributeMaxDynamicSharedMemorySize, 98304);
    cudaFuncSetAttribute(k_fwdH, cudaFuncAttributeMaxDynamicSharedMemorySize, 67584);
    cudaFuncSetAttribute(k_mix,  cudaFuncAttributeMaxDynamicSharedMemorySize, 131072);
    cudaFuncSetAttribute(k_invW, cudaFuncAttributeMaxDynamicSharedMemorySize, 67584);
    cudaFuncSetAttribute(k_mlp,  cudaFuncAttributeMaxDynamicSharedMemorySize, 115584);

    k_tab<<<1, 256>>>();
    k_film<<<PB, PC>>>(t, gamma_w, gamma_b, beta_w, beta_b);
    k_fwdW<<<NROWS / 32, 256, 98304>>>(x);
    k_fwdH<<<PB * PC, 256, 67584>>>();
    k_mix<<<128, 1024, 131072>>>(w1r, w1i, w2r, w2i);
    k_invH<<<PB * PC, 256>>>();
    k_invW<<<PB * PC, 256, 67584>>>();
    k_red1<<<PB, 32>>>();
    k_mlp<<<PB * PH, 256, 115584>>>(x, norm1_w, norm1_b,
                                    mlp_w1, mlp_b1, mlp_w2, mlp_b2);
    k_red2<<<PB, 256>>>();
    k_final<<<8192, 256>>>(x, out);
}

// round 6
// speedup vs baseline: 1.0208x; 1.0208x over previous
#include <cuda_runtime.h>
#include <math.h>

#define PB 8
#define PC 64
#define PH 256
#define PW 256
#define PKX 64
#define PKY 32
#define NROWS (PB*PC*PH)

// ---- scratch (device globals; no runtime allocation) ----
__device__ __align__(16) float  g_T[256*64];
__device__ __align__(16) float  g_cos[256];
__device__ __align__(16) float  g_sin[256];
__device__ __align__(16) float2 g_ct[256];            // (cos, sin) pairs
__device__ __align__(16) float2 g_X1[PB*PC*PH*PKY];   // after fwd-W  [b,c,h,ky]
__device__ __align__(16) float2 g_XF[PB*PC*PKX*PKY];  // after fwd-H  [b,c,kx',ky]
__device__ __align__(16) float2 g_OF[PB*PC*PKX*PKY];  // after mix
__device__ __align__(16) float2 g_Y1[PB*PC*PKY*PH];   // after inv-H  [b,c,ky,h]
__device__ __align__(16) float  g_y[PB*PC*PH*PW];     // spectral conv out
__device__ __align__(16) float  g_z[PB*PC*PH*PW];     // MLP out
__device__ __align__(16) float  g_p1[PB*PC*4*2];      // per-invW-block partials
__device__ __align__(16) float  g_p2[PB*PH*2];
__device__ __align__(16) float  g_s1[PB*2];
__device__ __align__(16) float  g_s2[PB*2];
__device__ __align__(16) float  g_gb[PB*PC*2];

__device__ __forceinline__ float gelu_f(float v) {
    return 0.5f * v * (1.0f + erff(v * 0.7071067811865476f));
}

// ---- twiddle tables ----
__global__ void k_tab() {
    int j = threadIdx.x;
    double sd, cd;
    sincospi((double)j * (2.0 / 256.0), &sd, &cd);
    g_cos[j] = (float)cd;
    g_sin[j] = (float)sd;
    g_ct[j] = make_float2((float)cd, (float)sd);
    for (int ky = 0; ky < 32; ++ky) {
        int idx = (ky * j) & 255;
        double s2, c2;
        sincospi((double)idx * (2.0 / 256.0), &s2, &c2);
        g_T[j * 64 + 2 * ky]     = (float)c2;
        g_T[j * 64 + 2 * ky + 1] = (float)(-s2);
    }
}

// ---- FiLM gamma/beta ----
__global__ void k_film(const float* __restrict__ t,
                       const float* __restrict__ gw, const float* __restrict__ gb,
                       const float* __restrict__ bw, const float* __restrict__ bb) {
    int b = blockIdx.x, o = threadIdx.x;
    float g = gb[o], be = bb[o];
    for (int c = 0; c < PC; ++c) {
        float tv = t[b * PC + c];
        g  += gw[o * PC + c] * tv;
        be += bw[o * PC + c] * tv;
    }
    g_gb[(b * PC + o) * 2]     = g;
    g_gb[(b * PC + o) * 2 + 1] = be;
}

// ---- forward DFT along W, truncated to 32 modes ----
__global__ void k_fwdW(const float* __restrict__ x) {
    extern __shared__ char smraw[];
    float* sx = (float*)smraw;           // 32*256
    float* sT = sx + 32 * 256;           // 256*64
    int tid = threadIdx.x;

    const float4* gx = (const float4*)(x + (size_t)blockIdx.x * 32 * 256);
    float4* sx4 = (float4*)sx;
    for (int i = tid; i < 2048; i += 256) sx4[i] = gx[i];
    const float4* gT4 = (const float4*)g_T;
    float4* sT4 = (float4*)sT;
    for (int i = tid; i < 4096; i += 256) sT4[i] = gT4[i];
    __syncthreads();

    int i2 = tid >> 4, j2 = tid & 15;
    float acc[2][4];
#pragma unroll
    for (int r = 0; r < 2; ++r)
#pragma unroll
        for (int u = 0; u < 4; ++u) acc[r][u] = 0.0f;

    const float* row0 = sx + (i2 * 2) * 256;
    const float* row1 = row0 + 256;
#pragma unroll 4
    for (int k = 0; k < 256; ++k) {
        float a0 = row0[k];
        float a1 = row1[k];
        float4 bv = *(const float4*)&sT[k * 64 + j2 * 4];
        acc[0][0] += a0 * bv.x; acc[0][1] += a0 * bv.y; acc[0][2] += a0 * bv.z; acc[0][3] += a0 * bv.w;
        acc[1][0] += a1 * bv.x; acc[1][1] += a1 * bv.y; acc[1][2] += a1 * bv.z; acc[1][3] += a1 * bv.w;
    }
    float* go = (float*)g_X1 + (size_t)blockIdx.x * 32 * 64;
#pragma unroll
    for (int r = 0; r < 2; ++r)
        *(float4*)&go[(i2 * 2 + r) * 64 + j2 * 4] =
            make_float4(acc[r][0], acc[r][1], acc[r][2], acc[r][3]);
}

// ---- forward DFT along H (64 kept rows), register-blocked 2kx x 4ky ----
__global__ void __launch_bounds__(256) k_fwdH() {
    extern __shared__ char smraw[];
    float2* sX = (float2*)smraw;             // 8192 float2
    float2* ct = (float2*)(smraw + 65536);   // 256 float2
    int tid = threadIdx.x, bc = blockIdx.x;

    const float4* src = (const float4*)(g_X1 + (size_t)bc * 8192);
    float4* dst = (float4*)sX;
    for (int i = tid; i < 4096; i += 256) dst[i] = src[i];
    ct[tid] = g_ct[tid];
    __syncthreads();

    int kxp0 = (tid >> 3) * 2;
    int ky0  = (tid & 7) * 4;
    int kxm0 = kxp0 + ((kxp0 >= 32) ? 192 : 0);
    int kxm1 = kxm0 + 1;

    float2 a0[4], a1[4];
#pragma unroll
    for (int j = 0; j < 4; ++j) {
        a0[j] = make_float2(0.f, 0.f);
        a1[j] = make_float2(0.f, 0.f);
    }

#pragma unroll 2
    for (int h = 0; h < 256; ++h) {
        float2 e0 = ct[(kxm0 * h) & 255];
        float2 e1 = ct[(kxm1 * h) & 255];
        float4 xA = *(const float4*)&sX[h * 32 + ky0];
        float4 xB = *(const float4*)&sX[h * 32 + ky0 + 2];
        float2 xv[4] = { {xA.x, xA.y}, {xA.z, xA.w}, {xB.x, xB.y}, {xB.z, xB.w} };
#pragma unroll
        for (int j = 0; j < 4; ++j) {
            // (xr + i xi)(c - i s)
            a0[j].x += xv[j].x * e0.x + xv[j].y * e0.y;
            a0[j].y += xv[j].y * e0.x - xv[j].x * e0.y;
            a1[j].x += xv[j].x * e1.x + xv[j].y * e1.y;
            a1[j].y += xv[j].y * e1.x - xv[j].x * e1.y;
        }
    }
    float2* o0 = g_XF + ((size_t)bc * 64 + kxp0) * 32 + ky0;
    float2* o1 = o0 + 32;
    *(float4*)&o0[0] = make_float4(a0[0].x, a0[0].y, a0[1].x, a0[1].y);
    *(float4*)&o0[2] = make_float4(a0[2].x, a0[2].y, a0[3].x, a0[3].y);
    *(float4*)&o1[0] = make_float4(a1[0].x, a1[0].y, a1[1].x, a1[1].y);
    *(float4*)&o1[2] = make_float4(a1[2].x, a1[2].y, a1[3].x, a1[3].y);
}

// ---- per-mode complex channel mixing ----
__global__ void __launch_bounds__(1024, 1)
k_mix(const float* __restrict__ w1r, const float* __restrict__ w1i,
      const float* __restrict__ w2r, const float* __restrict__ w2i) {
    extern __shared__ char smraw[];
    float2* sXF = (float2*)smraw;   // [(b*64+i)*32+ky], 16384 float2
    int kxp = blockIdx.x >> 1, half = blockIdx.x & 1;
    int tid = threadIdx.x;

    for (int i = tid; i < 16384; i += 1024) {
        int b = i >> 11, rest = i & 2047, ii = rest >> 5, kk = rest & 31;
        sXF[i] = g_XF[(((size_t)b * PC + ii) * PKX + kxp) * PKY + kk];
    }
    __syncthreads();

    int o = half * 32 + (tid >> 5), ky = tid & 31;
    const float* wr; const float* wi; int kxl;
    if (kxp < 32) { wr = w1r; wi = w1i; kxl = kxp; }
    else          { wr = w2r; wi = w2i; kxl = kxp - 32; }

    float ar[8], ai[8];
#pragma unroll
    for (int b = 0; b < 8; ++b) { ar[b] = 0.0f; ai[b] = 0.0f; }

    for (int i = 0; i < 64; ++i) {
        size_t widx = (((size_t)i * PC + o) * 32 + kxl) * 32 + ky;
        float wrv = wr[widx], wiv = wi[widx];
#pragma unroll
        for (int b = 0; b < 8; ++b) {
            float2 v = sXF[(b * 64 + i) * 32 + ky];
            ar[b] += v.x * wrv - v.y * wiv;
            ai[b] += v.x * wiv + v.y * wrv;
        }
    }
#pragma unroll
    for (int b = 0; b < 8; ++b)
        g_OF[(((size_t)b * PC + o) * PKX + kxp) * PKY + ky] = make_float2(ar[b], ai[b]);
}

// ---- inverse DFT along H, register-blocked 8h x 4ky ----
__global__ void __launch_bounds__(256) k_invH() {
    __shared__ float2 sOF[2048];
    __shared__ float2 ct[256];
    int tid = threadIdx.x, bc = blockIdx.x;

    const float4* src = (const float4*)(g_OF + (size_t)bc * 2048);
    float4* dst = (float4*)sOF;
    for (int i = tid; i < 1024; i += 256) dst[i] = src[i];
    ct[tid] = g_ct[tid];
    __syncthreads();

    int h0  = (tid >> 3) * 8;
    int ky0 = (tid & 7) * 4;

    float2 acc[8][4];
#pragma unroll
    for (int hh = 0; hh < 8; ++hh)
#pragma unroll
        for (int j = 0; j < 4; ++j) acc[hh][j] = make_float2(0.f, 0.f);

    for (int kxp = 0; kxp < 64; ++kxp) {
        int kxm = kxp + ((kxp >= 32) ? 192 : 0);
        float4 oA = *(const float4*)&sOF[kxp * 32 + ky0];
        float4 oB = *(const float4*)&sOF[kxp * 32 + ky0 + 2];
        float2 ov[4] = { {oA.x, oA.y}, {oA.z, oA.w}, {oB.x, oB.y}, {oB.z, oB.w} };
        int base = kxm * h0;
#pragma unroll
        for (int hh = 0; hh < 8; ++hh) {
            float2 e = ct[(base + kxm * hh) & 255];
#pragma unroll
            for (int j = 0; j < 4; ++j) {
                // (or + i oi)(c + i s)
                acc[hh][j].x += ov[j].x * e.x - ov[j].y * e.y;
                acc[hh][j].y += ov[j].x * e.y + ov[j].y * e.x;
            }
        }
    }
#pragma unroll
    for (int j = 0; j < 4; ++j) {
        float2* out = g_Y1 + (size_t)bc * 8192 + (ky0 + j) * 256 + h0;
#pragma unroll
        for (int hh = 0; hh < 8; hh += 2)
            *(float4*)&out[hh] = make_float4(acc[hh][j].x, acc[hh][j].y,
                                             acc[hh + 1][j].x, acc[hh + 1][j].y);
    }
}

// ---- inverse rfft along W as tiled GEMM (256h x 64w per block) + GN1 partials ----
__global__ void __launch_bounds__(256) k_invW() {
    extern __shared__ char smraw[];
    float2* sY = (float2*)smraw;               // 8192 float2 (64KB)
    float2* sW = (float2*)(smraw + 65536);     // 31*64 float2
    __shared__ float rbuf[16];
    int tid = threadIdx.x;
    int bc = blockIdx.x >> 2, wt = blockIdx.x & 3;
    int w0 = wt * 64;

    const float4* src = (const float4*)(g_Y1 + (size_t)bc * 8192);
    float4* dst = (float4*)sY;
    for (int i = tid; i < 4096; i += 256) dst[i] = src[i];

    const float inv = 1.0f / 65536.0f;
    for (int i = tid; i < 31 * 64; i += 256) {
        int ky = (i >> 6) + 1;
        int w  = w0 + (i & 63);
        int idx = (ky * w) & 255;
        sW[i] = make_float2(2.0f * inv * g_cos[idx], 2.0f * inv * g_sin[idx]);
    }
    __syncthreads();

    int h0  = (tid >> 3) * 8;
    int ww0 = (tid & 7) * 8;

    float acc[8][8];
#pragma unroll
    for (int hh = 0; hh < 8; ++hh) {
        float dc = inv * sY[h0 + hh].x;   // ky=0 DC term (real part)
#pragma unroll
        for (int ww = 0; ww < 8; ++ww) acc[hh][ww] = dc;
    }

    for (int ky = 1; ky <= 31; ++ky) {
        float2 av[8], bv[8];
        const float4* ap = (const float4*)&sY[ky * 256 + h0];
        const float4* bp = (const float4*)&sW[(ky - 1) * 64 + ww0];
#pragma unroll
        for (int u = 0; u < 4; ++u) {
            float4 t1 = ap[u];
            av[2 * u]     = make_float2(t1.x, t1.y);
            av[2 * u + 1] = make_float2(t1.z, t1.w);
            float4 t2 = bp[u];
            bv[2 * u]     = make_float2(t2.x, t2.y);
            bv[2 * u + 1] = make_float2(t2.z, t2.w);
        }
#pragma unroll
        for (int hh = 0; hh < 8; ++hh)
#pragma unroll
            for (int ww = 0; ww < 8; ++ww)
                acc[hh][ww] += av[hh].x * bv[ww].x - av[hh].y * bv[ww].y;
    }

    float s = 0.0f, s2 = 0.0f;
#pragma unroll
    for (int hh = 0; hh < 8; ++hh) {
        size_t base = (size_t)bc * 65536 + (size_t)(h0 + hh) * 256 + w0 + ww0;
        *(float4*)&g_y[base]     = make_float4(acc[hh][0], acc[hh][1], acc[hh][2], acc[hh][3]);
        *(float4*)&g_y[base + 4] = make_float4(acc[hh][4], acc[hh][5], acc[hh][6], acc[hh][7]);
#pragma unroll
        for (int ww = 0; ww < 8; ++ww) { s += acc[hh][ww]; s2 += acc[hh][ww] * acc[hh][ww]; }
    }

    for (int off = 16; off > 0; off >>= 1) {
        s  += __shfl_down_sync(0xffffffffu, s,  off);
        s2 += __shfl_down_sync(0xffffffffu, s2, off);
    }
    int lane = tid & 31, wid = tid >> 5;
    if (lane == 0) { rbuf[wid] = s; rbuf[wid + 8] = s2; }
    __syncthreads();
    if (tid == 0) {
        float S = 0.0f, S2 = 0.0f;
        for (int i = 0; i < 8; ++i) { S += rbuf[i]; S2 += rbuf[i + 8]; }
        g_p1[blockIdx.x * 2] = S;
        g_p1[blockIdx.x * 2 + 1] = S2;
    }
}

__global__ void k_red1() {
    __shared__ float rbuf[16];
    int b = blockIdx.x, tid = threadIdx.x;   // 256 threads, 256 partials per b
    float s  = g_p1[(b * 256 + tid) * 2];
    float s2 = g_p1[(b * 256 + tid) * 2 + 1];
    for (int off = 16; off > 0; off >>= 1) {
        s  += __shfl_down_sync(0xffffffffu, s,  off);
        s2 += __shfl_down_sync(0xffffffffu, s2, off);
    }
    int lane = tid & 31, wid = tid >> 5;
    if (lane == 0) { rbuf[wid] = s; rbuf[wid + 8] = s2; }
    __syncthreads();
    if (tid == 0) {
        float S = 0.0f, S2 = 0.0f;
        for (int i = 0; i < 8; ++i) { S += rbuf[i]; S2 += rbuf[i + 8]; }
        float mean = S * (1.0f / 4194304.0f);
        float var  = S2 * (1.0f / 4194304.0f) - mean * mean;
        g_s1[b * 2] = mean;
        g_s1[b * 2 + 1] = rsqrtf(var + 1e-5f);
    }
}

// ---- GN1 apply + residual + gelu + MLP + GN2 partials ----
__global__ void k_mlp(const float* __restrict__ x,
                      const float* __restrict__ nw, const float* __restrict__ nb,
                      const float* __restrict__ w1, const float* __restrict__ b1,
                      const float* __restrict__ w2, const float* __restrict__ b2) {
    extern __shared__ char smraw[];
    float* sy2  = (float*)smraw;        // [c][w]  64*256
    float* sh   = sy2 + 16384;          // [m][w]  32*256
    float* sw1  = sh + 8192;            // [c][m]
    float* sw2  = sw1 + 2048;           // [m][c]
    float* sb1  = sw2 + 2048;
    float* sb2v = sb1 + 32;
    float* snw  = sb2v + 64;
    float* snb  = snw + 64;
    __shared__ float rbuf[16];

    int tid = threadIdx.x;
    int b = blockIdx.x >> 8, h = blockIdx.x & 255;

    for (int i = tid; i < 2048; i += 256) {
        int c = i >> 5, m = i & 31;
        sw1[i] = w1[m * 64 + c];
        int m2 = i >> 6, c2 = i & 63;
        sw2[i] = w2[c2 * 32 + m2];
    }
    if (tid < 64) {
        sb2v[tid] = b2[tid];
        snw[tid] = nw[tid];
        snb[tid] = nb[tid];
        if (tid < 32) sb1[tid] = b1[tid];
    }
    float mean1 = g_s1[b * 2], rstd1 = g_s1[b * 2 + 1];
    __syncthreads();

    for (int i = tid; i < 16384; i += 256) {
        int c = i >> 8, wc = i & 255;
        size_t gid = (size_t)(b * 64 + c) * 65536 + (size_t)h * 256 + wc;
        float tv = (g_y[gid] - mean1) * rstd1 * snw[c] + snb[c] + x[gid];
        sy2[i] = gelu_f(tv);
    }
    __syncthreads();

    int wg = tid & 31;
    int wA = wg * 4, wB = wA + 128;

    {   // layer 1: 32x64 @ 64x256
        int tm = tid >> 5, m0 = tm * 4;
        float acc[4][8];
#pragma unroll
        for (int mm = 0; mm < 4; ++mm)
#pragma unroll
            for (int ww = 0; ww < 8; ++ww) acc[mm][ww] = 0.0f;
        for (int c = 0; c < 64; ++c) {
            float4 wv = *(const float4*)&sw1[c * 32 + m0];
            float4 y0 = *(const float4*)&sy2[c * 256 + wA];
            float4 y1 = *(const float4*)&sy2[c * 256 + wB];
            float wa[4] = { wv.x, wv.y, wv.z, wv.w };
            float yv[8] = { y0.x, y0.y, y0.z, y0.w, y1.x, y1.y, y1.z, y1.w };
#pragma unroll
            for (int mm = 0; mm < 4; ++mm)
#pragma unroll
                for (int ww = 0; ww < 8; ++ww) acc[mm][ww] += wa[mm] * yv[ww];
        }
#pragma unroll
        for (int mm = 0; mm < 4; ++mm) {
            float bb = sb1[m0 + mm];
#pragma unroll
            for (int ww = 0; ww < 8; ++ww) {
                int wcol = (ww < 4) ? (wA + ww) : (wB + ww - 4);
                sh[(m0 + mm) * 256 + wcol] = gelu_f(acc[mm][ww] + bb);
            }
        }
    }
    __syncthreads();

    float s = 0.0f, s2 = 0.0f;
    {   // layer 2: 64x32 @ 32x256 + stats
        int tc = tid >> 5, c0 = tc * 8;
        float acc2[8][8];
#pragma unroll
        for (int cc = 0; cc < 8; ++cc)
#pragma unroll
            for (int ww = 0; ww < 8; ++ww) acc2[cc][ww] = 0.0f;
        for (int m = 0; m < 32; ++m) {
            float4 a0 = *(const float4*)&sw2[m * 64 + c0];
            float4 a1 = *(const float4*)&sw2[m * 64 + c0 + 4];
            float4 h0 = *(const float4*)&sh[m * 256 + wA];
            float4 h1 = *(const float4*)&sh[m * 256 + wB];
            float wa[8] = { a0.x, a0.y, a0.z, a0.w, a1.x, a1.y, a1.z, a1.w };
            float hv[8] = { h0.x, h0.y, h0.z, h0.w, h1.x, h1.y, h1.z, h1.w };
#pragma unroll
            for (int cc = 0; cc < 8; ++cc)
#pragma unroll
                for (int ww = 0; ww < 8; ++ww) acc2[cc][ww] += wa[cc] * hv[ww];
        }
#pragma unroll
        for (int cc = 0; cc < 8; ++cc) {
            float bb = sb2v[c0 + cc];
            float o[8];
#pragma unroll
            for (int ww = 0; ww < 8; ++ww) {
                o[ww] = acc2[cc][ww] + bb;
                s += o[ww];
                s2 += o[ww] * o[ww];
            }
            size_t gbase = (size_t)(b * 64 + c0 + cc) * 65536 + (size_t)h * 256;
            *(float4*)&g_z[gbase + wA] = make_float4(o[0], o[1], o[2], o[3]);
            *(float4*)&g_z[gbase + wB] = make_float4(o[4], o[5], o[6], o[7]);
        }
    }

    for (int off = 16; off > 0; off >>= 1) {
        s  += __shfl_down_sync(0xffffffffu, s,  off);
        s2 += __shfl_down_sync(0xffffffffu, s2, off);
    }
    int lane = tid & 31, widx = tid >> 5;
    if (lane == 0) { rbuf[widx] = s; rbuf[widx + 8] = s2; }
    __syncthreads();
    if (tid == 0) {
        float S = 0.0f, S2 = 0.0f;
        for (int i = 0; i < 8; ++i) { S += rbuf[i]; S2 += rbuf[i + 8]; }
        g_p2[blockIdx.x * 2] = S;
        g_p2[blockIdx.x * 2 + 1] = S2;
    }
}

__global__ void k_red2() {
    __shared__ float rbuf[16];
    int b = blockIdx.x, tid = threadIdx.x;
    float s  = g_p2[(b * 256 + tid) * 2];
    float s2 = g_p2[(b * 256 + tid) * 2 + 1];
    for (int off = 16; off > 0; off >>= 1) {
        s  += __shfl_down_sync(0xffffffffu, s,  off);
        s2 += __shfl_down_sync(0xffffffffu, s2, off);
    }
    int lane = tid & 31, wid = tid >> 5;
    if (lane == 0) { rbuf[wid] = s; rbuf[wid + 8] = s2; }
    __syncthreads();
    if (tid == 0) {
        float S = 0.0f, S2 = 0.0f;
        for (int i = 0; i < 8; ++i) { S += rbuf[i]; S2 += rbuf[i + 8]; }
        float mean = S * (1.0f / 4194304.0f);
        float var  = S2 * (1.0f / 4194304.0f) - mean * mean;
        g_s2[b * 2] = mean;
        g_s2[b * 2 + 1] = rsqrtf(var + 1e-5f);
    }
}

// ---- final: FiLM GN + skip2 ----
__global__ void k_final(const float* __restrict__ x, float* __restrict__ out) {
    int gi = blockIdx.x * 256 + threadIdx.x;
#pragma unroll
    for (int u = 0; u < 4; ++u) {
        size_t i4 = (size_t)gi + (size_t)u * 2097152;
        size_t e = i4 * 4;
        int b = (int)(e >> 22);
        int c = (int)((e >> 16) & 63);
        float mean = g_s2[b * 2], rstd = g_s2[b * 2 + 1];
        float ga = g_gb[(b * 64 + c) * 2], be = g_gb[(b * 64 + c) * 2 + 1];
        float4 zv = ((const float4*)g_z)[i4];
        float4 xv = ((const float4*)x)[i4];
        float4 ov;
        ov.x = ga * (zv.x - mean) * rstd + be + gelu_f(xv.x);
        ov.y = ga * (zv.y - mean) * rstd + be + gelu_f(xv.y);
        ov.z = ga * (zv.z - mean) * rstd + be + gelu_f(xv.z);
        ov.w = ga * (zv.w - mean) * rstd + be + gelu_f(xv.w);
        ((float4*)out)[i4] = ov;
    }
}

extern "C" void kernel_launch(void* const* d_in, const int* in_sizes, int n_in,
                              void* d_out, int out_size) {
    const float* x       = (const float*)d_in[0];
    const float* t       = (const float*)d_in[1];
    const float* w1r     = (const float*)d_in[2];
    const float* w1i     = (const float*)d_in[3];
    const float* w2r     = (const float*)d_in[4];
    const float* w2i     = (const float*)d_in[5];
    const float* norm1_w = (const float*)d_in[6];
    const float* norm1_b = (const float*)d_in[7];
    const float* mlp_w1  = (const float*)d_in[8];
    const float* mlp_b1  = (const float*)d_in[9];
    const float* mlp_w2  = (const float*)d_in[10];
    const float* mlp_b2  = (const float*)d_in[11];
    const float* gamma_w = (const float*)d_in[12];
    const float* gamma_b = (const float*)d_in[13];
    const float* beta_w  = (const float*)d_in[14];
    const float* beta_b  = (const float*)d_in[15];
    float* out = (float*)d_out;

    cudaFuncSetAttribute(k_fwdW, cudaFuncAttributeMaxDynamicSharedMemorySize, 98304);
    cudaFuncSetAttribute(k_fwdH, cudaFuncAttributeMaxDynamicSharedMemorySize, 67584);
    cudaFuncSetAttribute(k_mix,  cudaFuncAttributeMaxDynamicSharedMemorySize, 131072);
    cudaFuncSetAttribute(k_invW, cudaFuncAttributeMaxDynamicSharedMemorySize, 81408);
    cudaFuncSetAttribute(k_mlp,  cudaFuncAttributeMaxDynamicSharedMemorySize, 115584);

    k_tab<<<1, 256>>>();
    k_film<<<PB, PC>>>(t, gamma_w, gamma_b, beta_w, beta_b);
    k_fwdW<<<NROWS / 32, 256, 98304>>>(x);
    k_fwdH<<<PB * PC, 256, 67584>>>();
    k_mix<<<128, 1024, 131072>>>(w1r, w1i, w2r, w2i);
    k_invH<<<PB * PC, 256>>>();
    k_invW<<<PB * PC * 4, 256, 81408>>>();
    k_red1<<<PB, 256>>>();
    k_mlp<<<PB * PH, 256, 115584>>>(x, norm1_w, norm1_b,
                                    mlp_w1, mlp_b1, mlp_w2, mlp_b2);
    k_red2<<<PB, 256>>>();
    k_final<<<8192, 256>>>(x, out);
}

// round 7
// speedup vs baseline: 1.3673x; 1.3394x over previous
#include <cuda_runtime.h>
#include <math.h>

#define PB 8
#define PC 64
#define PH 256
#define PW 256
#define PKX 64
#define PKY 32
#define NROWS (PB*PC*PH)

// ---- scratch (device globals; no runtime allocation) ----
__device__ __align__(16) float  g_T[256*64];
__device__ __align__(16) float  g_cos[256];
__device__ __align__(16) float  g_sin[256];
__device__ __align__(16) float2 g_ct[256];            // (cos, sin) pairs
__device__ __align__(16) float2 g_X1[PB*PC*PH*PKY];   // after fwd-W  [b,c,h,ky]
__device__ __align__(16) float2 g_XF[PB*PC*PKX*PKY];  // after fwd-H  [b,c,kx',ky]
__device__ __align__(16) float2 g_OF[PB*PC*PKX*PKY];  // after mix
__device__ __align__(16) float2 g_Y1[PB*PC*PKY*PH];   // after inv-H  [b,c,ky,h]
__device__ __align__(16) float  g_y[PB*PC*PH*PW];     // spectral conv out
__device__ __align__(16) float  g_z[PB*PC*PH*PW];     // MLP out
__device__ __align__(16) float  g_p1[PB*PC*4*2];      // per-invW-block partials
__device__ __align__(16) float  g_p2[PB*PH*2];
__device__ __align__(16) float  g_s1[PB*2];
__device__ __align__(16) float  g_s2[PB*2];
__device__ __align__(16) float  g_gb[PB*PC*2];

__device__ __forceinline__ float gelu_f(float v) {
    return 0.5f * v * (1.0f + erff(v * 0.7071067811865476f));
}

// ---- twiddle tables ----
__global__ void k_tab() {
    int j = threadIdx.x;
    double sd, cd;
    sincospi((double)j * (2.0 / 256.0), &sd, &cd);
    g_cos[j] = (float)cd;
    g_sin[j] = (float)sd;
    g_ct[j] = make_float2((float)cd, (float)sd);
    for (int ky = 0; ky < 32; ++ky) {
        int idx = (ky * j) & 255;
        double s2, c2;
        sincospi((double)idx * (2.0 / 256.0), &s2, &c2);
        g_T[j * 64 + 2 * ky]     = (float)c2;
        g_T[j * 64 + 2 * ky + 1] = (float)(-s2);
    }
}

// ---- FiLM gamma/beta ----
__global__ void k_film(const float* __restrict__ t,
                       const float* __restrict__ gw, const float* __restrict__ gb,
                       const float* __restrict__ bw, const float* __restrict__ bb) {
    int b = blockIdx.x, o = threadIdx.x;
    float g = gb[o], be = bb[o];
    for (int c = 0; c < PC; ++c) {
        float tv = t[b * PC + c];
        g  += gw[o * PC + c] * tv;
        be += bw[o * PC + c] * tv;
    }
    g_gb[(b * PC + o) * 2]     = g;
    g_gb[(b * PC + o) * 2 + 1] = be;
}

// ---- forward DFT along W, radix-2: K=128, even ky uses u0=x+xh, odd uses u1=x-xh ----
__global__ void __launch_bounds__(256) k_fwdW(const float* __restrict__ x) {
    extern __shared__ char smraw[];
    float2* su = (float2*)smraw;            // [row][w<128] (u0,u1)  32KB
    float*  sT = (float*)(smraw + 32768);   // [w<128][64]           32KB
    int tid = threadIdx.x;
    size_t base = (size_t)blockIdx.x * 32 * 256;

    for (int i = tid; i < 1024; i += 256) {
        int row = i >> 5, w4 = (i & 31) * 4;
        float4 a = *(const float4*)&x[base + row * 256 + w4];
        float4 b = *(const float4*)&x[base + row * 256 + w4 + 128];
        float4* d = (float4*)&su[row * 128 + w4];
        d[0] = make_float4(a.x + b.x, a.x - b.x, a.y + b.y, a.y - b.y);
        d[1] = make_float4(a.z + b.z, a.z - b.z, a.w + b.w, a.w - b.w);
    }
    const float4* gT4 = (const float4*)g_T;
    float4* sT4 = (float4*)sT;
    for (int i = tid; i < 2048; i += 256) sT4[i] = gT4[i];   // rows 0..127
    __syncthreads();

    int i2 = tid >> 4, j2 = tid & 15;
    float acc[2][4];
#pragma unroll
    for (int r = 0; r < 2; ++r)
#pragma unroll
        for (int u = 0; u < 4; ++u) acc[r][u] = 0.0f;

    const float2* r0 = su + (i2 * 2) * 128;
    const float2* r1 = r0 + 128;
#pragma unroll 4
    for (int k = 0; k < 128; ++k) {
        float2 u0 = r0[k];
        float2 u1 = r1[k];
        float4 bv = *(const float4*)&sT[k * 64 + j2 * 4];
        // modes 2*j2 (even -> .x) and 2*j2+1 (odd -> .y)
        acc[0][0] += u0.x * bv.x; acc[0][1] += u0.x * bv.y;
        acc[0][2] += u0.y * bv.z; acc[0][3] += u0.y * bv.w;
        acc[1][0] += u1.x * bv.x; acc[1][1] += u1.x * bv.y;
        acc[1][2] += u1.y * bv.z; acc[1][3] += u1.y * bv.w;
    }
    float* go = (float*)g_X1 + (size_t)blockIdx.x * 32 * 64;
#pragma unroll
    for (int r = 0; r < 2; ++r)
        *(float4*)&go[(i2 * 2 + r) * 64 + j2 * 4] =
            make_float4(acc[r][0], acc[r][1], acc[r][2], acc[r][3]);
}

// ---- forward DFT along H, radix-2 over h ----
__global__ void __launch_bounds__(256) k_fwdH() {
    extern __shared__ char smraw[];
    float2* sv0 = (float2*)smraw;              // h<128, even-kx operand (sum)
    float2* sv1 = sv0 + 4096;                  // odd-kx operand (diff)
    float2* ct  = (float2*)(smraw + 65536);
    int tid = threadIdx.x, bc = blockIdx.x;

    const float4* src = (const float4*)(g_X1 + (size_t)bc * 8192);
    float4* d0 = (float4*)sv0;
    float4* d1 = (float4*)sv1;
    for (int i = tid; i < 2048; i += 256) {
        float4 a = src[i];
        float4 b = src[i + 2048];               // h+128
        d0[i] = make_float4(a.x + b.x, a.y + b.y, a.z + b.z, a.w + b.w);
        d1[i] = make_float4(a.x - b.x, a.y - b.y, a.z - b.z, a.w - b.w);
    }
    ct[tid] = g_ct[tid];
    __syncthreads();

    int kxp0 = (tid >> 3) * 2;                 // even
    int ky0  = (tid & 7) * 4;
    int kxm0 = kxp0 + ((kxp0 >= 32) ? 192 : 0);  // even
    int kxm1 = kxm0 + 1;                          // odd

    float2 a0[4], a1[4];
#pragma unroll
    for (int j = 0; j < 4; ++j) {
        a0[j] = make_float2(0.f, 0.f);
        a1[j] = make_float2(0.f, 0.f);
    }

#pragma unroll 2
    for (int h = 0; h < 128; ++h) {
        float2 e0 = ct[(kxm0 * h) & 255];
        float2 e1 = ct[(kxm1 * h) & 255];
        float4 xA0 = *(const float4*)&sv0[h * 32 + ky0];
        float4 xB0 = *(const float4*)&sv0[h * 32 + ky0 + 2];
        float4 xA1 = *(const float4*)&sv1[h * 32 + ky0];
        float4 xB1 = *(const float4*)&sv1[h * 32 + ky0 + 2];
        float2 v0[4] = { {xA0.x, xA0.y}, {xA0.z, xA0.w}, {xB0.x, xB0.y}, {xB0.z, xB0.w} };
        float2 v1[4] = { {xA1.x, xA1.y}, {xA1.z, xA1.w}, {xB1.x, xB1.y}, {xB1.z, xB1.w} };
#pragma unroll
        for (int j = 0; j < 4; ++j) {
            // (xr + i xi)(c - i s)
            a0[j].x += v0[j].x * e0.x + v0[j].y * e0.y;
            a0[j].y += v0[j].y * e0.x - v0[j].x * e0.y;
            a1[j].x += v1[j].x * e1.x + v1[j].y * e1.y;
            a1[j].y += v1[j].y * e1.x - v1[j].x * e1.y;
        }
    }
    float2* o0 = g_XF + ((size_t)bc * 64 + kxp0) * 32 + ky0;
    float2* o1 = o0 + 32;
    *(float4*)&o0[0] = make_float4(a0[0].x, a0[0].y, a0[1].x, a0[1].y);
    *(float4*)&o0[2] = make_float4(a0[2].x, a0[2].y, a0[3].x, a0[3].y);
    *(float4*)&o1[0] = make_float4(a1[0].x, a1[0].y, a1[1].x, a1[1].y);
    *(float4*)&o1[2] = make_float4(a1[2].x, a1[2].y, a1[3].x, a1[3].y);
}

// ---- per-mode complex channel mixing ----
__global__ void __launch_bounds__(1024, 1)
k_mix(const float* __restrict__ w1r, const float* __restrict__ w1i,
      const float* __restrict__ w2r, const float* __restrict__ w2i) {
    extern __shared__ char smraw[];
    float2* sXF = (float2*)smraw;   // [(b*64+i)*32+ky], 16384 float2
    int kxp = blockIdx.x >> 1, half = blockIdx.x & 1;
    int tid = threadIdx.x;

    for (int i = tid; i < 16384; i += 1024) {
        int b = i >> 11, rest = i & 2047, ii = rest >> 5, kk = rest & 31;
        sXF[i] = g_XF[(((size_t)b * PC + ii) * PKX + kxp) * PKY + kk];
    }
    __syncthreads();

    int o = half * 32 + (tid >> 5), ky = tid & 31;
    const float* wr; const float* wi; int kxl;
    if (kxp < 32) { wr = w1r; wi = w1i; kxl = kxp; }
    else          { wr = w2r; wi = w2i; kxl = kxp - 32; }

    float ar[8], ai[8];
#pragma unroll
    for (int b = 0; b < 8; ++b) { ar[b] = 0.0f; ai[b] = 0.0f; }

    for (int i = 0; i < 64; ++i) {
        size_t widx = (((size_t)i * PC + o) * 32 + kxl) * 32 + ky;
        float wrv = wr[widx], wiv = wi[widx];
#pragma unroll
        for (int b = 0; b < 8; ++b) {
            float2 v = sXF[(b * 64 + i) * 32 + ky];
            ar[b] += v.x * wrv - v.y * wiv;
            ai[b] += v.x * wiv + v.y * wrv;
        }
    }
#pragma unroll
    for (int b = 0; b < 8; ++b)
        g_OF[(((size_t)b * PC + o) * PKX + kxp) * PKY + ky] = make_float2(ar[b], ai[b]);
}

// ---- inverse DFT along H, radix-2: Se/So over kx parity, emit h and h+128 ----
__global__ void __launch_bounds__(256) k_invH() {
    __shared__ float2 sOF[2048];
    __shared__ float2 ct[256];
    int tid = threadIdx.x, bc = blockIdx.x;

    const float4* src = (const float4*)(g_OF + (size_t)bc * 2048);
    float4* dst = (float4*)sOF;
    for (int i = tid; i < 1024; i += 256) dst[i] = src[i];
    ct[tid] = g_ct[tid];
    __syncthreads();

    int h0  = (tid >> 3) * 4;     // h<128
    int ky0 = (tid & 7) * 4;

    float2 ae[4][4], ao[4][4];
#pragma unroll
    for (int hh = 0; hh < 4; ++hh)
#pragma unroll
        for (int j = 0; j < 4; ++j) {
            ae[hh][j] = make_float2(0.f, 0.f);
            ao[hh][j] = make_float2(0.f, 0.f);
        }

    for (int kxp = 0; kxp < 64; kxp += 2) {
        int kxm = kxp + ((kxp >= 32) ? 192 : 0);   // even
        float4 eA = *(const float4*)&sOF[kxp * 32 + ky0];
        float4 eB = *(const float4*)&sOF[kxp * 32 + ky0 + 2];
        float4 oA = *(const float4*)&sOF[(kxp + 1) * 32 + ky0];
        float4 oB = *(const float4*)&sOF[(kxp + 1) * 32 + ky0 + 2];
        float2 ove[4] = { {eA.x, eA.y}, {eA.z, eA.w}, {eB.x, eB.y}, {eB.z, eB.w} };
        float2 ovo[4] = { {oA.x, oA.y}, {oA.z, oA.w}, {oB.x, oB.y}, {oB.z, oB.w} };
#pragma unroll
        for (int hh = 0; hh < 4; ++hh) {
            int h = h0 + hh;
            float2 te = ct[(kxm * h) & 255];
            float2 to = ct[((kxm + 1) * h) & 255];
#pragma unroll
            for (int j = 0; j < 4; ++j) {
                ae[hh][j].x += ove[j].x * te.x - ove[j].y * te.y;
                ae[hh][j].y += ove[j].x * te.y + ove[j].y * te.x;
                ao[hh][j].x += ovo[j].x * to.x - ovo[j].y * to.y;
                ao[hh][j].y += ovo[j].x * to.y + ovo[j].y * to.x;
            }
        }
    }
#pragma unroll
    for (int j = 0; j < 4; ++j) {
        float2* out = g_Y1 + (size_t)bc * 8192 + (ky0 + j) * 256 + h0;
#pragma unroll
        for (int hh = 0; hh < 4; hh += 2) {
            *(float4*)&out[hh] = make_float4(
                ae[hh][j].x + ao[hh][j].x,     ae[hh][j].y + ao[hh][j].y,
                ae[hh+1][j].x + ao[hh+1][j].x, ae[hh+1][j].y + ao[hh+1][j].y);
            *(float4*)&out[hh + 128] = make_float4(
                ae[hh][j].x - ao[hh][j].x,     ae[hh][j].y - ao[hh][j].y,
                ae[hh+1][j].x - ao[hh+1][j].x, ae[hh+1][j].y - ao[hh+1][j].y);
        }
    }
}

// ---- inverse rfft along W, radix-2: Se/So over ky parity, emit w and w+128 ----
__global__ void __launch_bounds__(256) k_invW() {
    extern __shared__ char smraw[];
    float2* sY = (float2*)smraw;               // 8192 float2 (64KB)
    float2* sW = (float2*)(smraw + 65536);     // 31*32 float2
    __shared__ float rbuf[16];
    int tid = threadIdx.x;
    int bc = blockIdx.x >> 2, wt = blockIdx.x & 3;
    int w0 = wt * 32;                           // base-w tile; outputs w0.. and w0+128..

    const float4* src = (const float4*)(g_Y1 + (size_t)bc * 8192);
    float4* dst = (float4*)sY;
    for (int i = tid; i < 4096; i += 256) dst[i] = src[i];

    const float inv = 1.0f / 65536.0f;
    for (int i = tid; i < 31 * 32; i += 256) {
        int ky = (i >> 5) + 1;
        int w  = w0 + (i & 31);
        int idx = (ky * w) & 255;
        sW[i] = make_float2(2.0f * inv * g_cos[idx], 2.0f * inv * g_sin[idx]);
    }
    __syncthreads();

    int h0  = (tid >> 3) * 8;
    int wth = (tid & 7) * 4;

    float se[8][4], so[8][4], dc[8];
#pragma unroll
    for (int hh = 0; hh < 8; ++hh) {
        dc[hh] = inv * sY[h0 + hh].x;
#pragma unroll
        for (int ww = 0; ww < 4; ++ww) { se[hh][ww] = 0.f; so[hh][ww] = 0.f; }
    }

    for (int ky = 1; ky < 31; ky += 2) {
        {   // odd ky -> so
            float2 av[8], bv[4];
            const float4* ap = (const float4*)&sY[ky * 256 + h0];
#pragma unroll
            for (int u = 0; u < 4; ++u) {
                float4 t1 = ap[u];
                av[2*u] = make_float2(t1.x, t1.y);
                av[2*u+1] = make_float2(t1.z, t1.w);
            }
            const float4* bp = (const float4*)&sW[(ky - 1) * 32 + wth];
            float4 t2 = bp[0], t3 = bp[1];
            bv[0] = make_float2(t2.x, t2.y); bv[1] = make_float2(t2.z, t2.w);
            bv[2] = make_float2(t3.x, t3.y); bv[3] = make_float2(t3.z, t3.w);
#pragma unroll
            for (int hh = 0; hh < 8; ++hh)
#pragma unroll
                for (int ww = 0; ww < 4; ++ww)
                    so[hh][ww] += av[hh].x * bv[ww].x - av[hh].y * bv[ww].y;
        }
        {   // even ky+1 -> se
            float2 av[8], bv[4];
            const float4* ap = (const float4*)&sY[(ky + 1) * 256 + h0];
#pragma unroll
            for (int u = 0; u < 4; ++u) {
                float4 t1 = ap[u];
                av[2*u] = make_float2(t1.x, t1.y);
                av[2*u+1] = make_float2(t1.z, t1.w);
            }
            const float4* bp = (const float4*)&sW[ky * 32 + wth];
            float4 t2 = bp[0], t3 = bp[1];
            bv[0] = make_float2(t2.x, t2.y); bv[1] = make_float2(t2.z, t2.w);
            bv[2] = make_float2(t3.x, t3.y); bv[3] = make_float2(t3.z, t3.w);
#pragma unroll
            for (int hh = 0; hh < 8; ++hh)
#pragma unroll
                for (int ww = 0; ww < 4; ++ww)
                    se[hh][ww] += av[hh].x * bv[ww].x - av[hh].y * bv[ww].y;
        }
    }
    {   // ky = 31 (odd) -> so
        float2 av[8], bv[4];
        const float4* ap = (const float4*)&sY[31 * 256 + h0];
#pragma unroll
        for (int u = 0; u < 4; ++u) {
            float4 t1 = ap[u];
            av[2*u] = make_float2(t1.x, t1.y);
            av[2*u+1] = make_float2(t1.z, t1.w);
        }
        const float4* bp = (const float4*)&sW[30 * 32 + wth];
        float4 t2 = bp[0], t3 = bp[1];
        bv[0] = make_float2(t2.x, t2.y); bv[1] = make_float2(t2.z, t2.w);
        bv[2] = make_float2(t3.x, t3.y); bv[3] = make_float2(t3.z, t3.w);
#pragma unroll
        for (int hh = 0; hh < 8; ++hh)
#pragma unroll
            for (int ww = 0; ww < 4; ++ww)
                so[hh][ww] += av[hh].x * bv[ww].x - av[hh].y * bv[ww].y;
    }

    float s = 0.0f, s2 = 0.0f;
#pragma unroll
    for (int hh = 0; hh < 8; ++hh) {
        float lo[4], hi[4];
#pragma unroll
        for (int ww = 0; ww < 4; ++ww) {
            lo[ww] = dc[hh] + se[hh][ww] + so[hh][ww];
            hi[ww] = dc[hh] + se[hh][ww] - so[hh][ww];
            s += lo[ww] + hi[ww];
            s2 += lo[ww] * lo[ww] + hi[ww] * hi[ww];
        }
        size_t base = (size_t)bc * 65536 + (size_t)(h0 + hh) * 256 + w0 + wth;
        *(float4*)&g_y[base]       = make_float4(lo[0], lo[1], lo[2], lo[3]);
        *(float4*)&g_y[base + 128] = make_float4(hi[0], hi[1], hi[2], hi[3]);
    }

    for (int off = 16; off > 0; off >>= 1) {
        s  += __shfl_down_sync(0xffffffffu, s,  off);
        s2 += __shfl_down_sync(0xffffffffu, s2, off);
    }
    int lane = tid & 31, wid = tid >> 5;
    if (lane == 0) { rbuf[wid] = s; rbuf[wid + 8] = s2; }
    __syncthreads();
    if (tid == 0) {
        float S = 0.0f, S2 = 0.0f;
        for (int i = 0; i < 8; ++i) { S += rbuf[i]; S2 += rbuf[i + 8]; }
        g_p1[blockIdx.x * 2] = S;
        g_p1[blockIdx.x * 2 + 1] = S2;
    }
}

__global__ void k_red1() {
    __shared__ float rbuf[16];
    int b = blockIdx.x, tid = threadIdx.x;   // 256 partials per b
    float s  = g_p1[(b * 256 + tid) * 2];
    float s2 = g_p1[(b * 256 + tid) * 2 + 1];
    for (int off = 16; off > 0; off >>= 1) {
        s  += __shfl_down_sync(0xffffffffu, s,  off);
        s2 += __shfl_down_sync(0xffffffffu, s2, off);
    }
    int lane = tid & 31, wid = tid >> 5;
    if (lane == 0) { rbuf[wid] = s; rbuf[wid + 8] = s2; }
    __syncthreads();
    if (tid == 0) {
        float S = 0.0f, S2 = 0.0f;
        for (int i = 0; i < 8; ++i) { S += rbuf[i]; S2 += rbuf[i + 8]; }
        float mean = S * (1.0f / 4194304.0f);
        float var  = S2 * (1.0f / 4194304.0f) - mean * mean;
        g_s1[b * 2] = mean;
        g_s1[b * 2 + 1] = rsqrtf(var + 1e-5f);
    }
}

// ---- GN1 apply + residual + gelu + MLP + GN2 partials ----
__global__ void k_mlp(const float* __restrict__ x,
                      const float* __restrict__ nw, const float* __restrict__ nb,
                      const float* __restrict__ w1, const float* __restrict__ b1,
                      const float* __restrict__ w2, const float* __restrict__ b2) {
    extern __shared__ char smraw[];
    float* sy2  = (float*)smraw;        // [c][w]  64*256
    float* sh   = sy2 + 16384;          // [m][w]  32*256
    float* sw1  = sh + 8192;            // [c][m]
    float* sw2  = sw1 + 2048;           // [m][c]
    float* sb1  = sw2 + 2048;
    float* sb2v = sb1 + 32;
    float* snw  = sb2v + 64;
    float* snb  = snw + 64;
    __shared__ float rbuf[16];

    int tid = threadIdx.x;
    int b = blockIdx.x >> 8, h = blockIdx.x & 255;

    for (int i = tid; i < 2048; i += 256) {
        int c = i >> 5, m = i & 31;
        sw1[i] = w1[m * 64 + c];
        int m2 = i >> 6, c2 = i & 63;
        sw2[i] = w2[c2 * 32 + m2];
    }
    if (tid < 64) {
        sb2v[tid] = b2[tid];
        snw[tid] = nw[tid];
        snb[tid] = nb[tid];
        if (tid < 32) sb1[tid] = b1[tid];
    }
    float mean1 = g_s1[b * 2], rstd1 = g_s1[b * 2 + 1];
    __syncthreads();

    for (int i = tid; i < 16384; i += 256) {
        int c = i >> 8, wc = i & 255;
        size_t gid = (size_t)(b * 64 + c) * 65536 + (size_t)h * 256 + wc;
        float tv = (g_y[gid] - mean1) * rstd1 * snw[c] + snb[c] + x[gid];
        sy2[i] = gelu_f(tv);
    }
    __syncthreads();

    int wg = tid & 31;
    int wA = wg * 4, wB = wA + 128;

    {   // layer 1: 32x64 @ 64x256
        int tm = tid >> 5, m0 = tm * 4;
        float acc[4][8];
#pragma unroll
        for (int mm = 0; mm < 4; ++mm)
#pragma unroll
            for (int ww = 0; ww < 8; ++ww) acc[mm][ww] = 0.0f;
        for (int c = 0; c < 64; ++c) {
            float4 wv = *(const float4*)&sw1[c * 32 + m0];
            float4 y0 = *(const float4*)&sy2[c * 256 + wA];
            float4 y1 = *(const float4*)&sy2[c * 256 + wB];
            float wa[4] = { wv.x, wv.y, wv.z, wv.w };
            float yv[8] = { y0.x, y0.y, y0.z, y0.w, y1.x, y1.y, y1.z, y1.w };
#pragma unroll
            for (int mm = 0; mm < 4; ++mm)
#pragma unroll
                for (int ww = 0; ww < 8; ++ww) acc[mm][ww] += wa[mm] * yv[ww];
        }
#pragma unroll
        for (int mm = 0; mm < 4; ++mm) {
            float bb = sb1[m0 + mm];
#pragma unroll
            for (int ww = 0; ww < 8; ++ww) {
                int wcol = (ww < 4) ? (wA + ww) : (wB + ww - 4);
                sh[(m0 + mm) * 256 + wcol] = gelu_f(acc[mm][ww] + bb);
            }
        }
    }
    __syncthreads();

    float s = 0.0f, s2 = 0.0f;
    {   // layer 2: 64x32 @ 32x256 + stats
        int tc = tid >> 5, c0 = tc * 8;
        float acc2[8][8];
#pragma unroll
        for (int cc = 0; cc < 8; ++cc)
#pragma unroll
            for (int ww = 0; ww < 8; ++ww) acc2[cc][ww] = 0.0f;
        for (int m = 0; m < 32; ++m) {
            float4 a0 = *(const float4*)&sw2[m * 64 + c0];
            float4 a1 = *(const float4*)&sw2[m * 64 + c0 + 4];
            float4 h0 = *(const float4*)&sh[m * 256 + wA];
            float4 h1 = *(const float4*)&sh[m * 256 + wB];
            float wa[8] = { a0.x, a0.y, a0.z, a0.w, a1.x, a1.y, a1.z, a1.w };
            float hv[8] = { h0.x, h0.y, h0.z, h0.w, h1.x, h1.y, h1.z, h1.w };
#pragma unroll
            for (int cc = 0; cc < 8; ++cc)
#pragma unroll
                for (int ww = 0; ww < 8; ++ww) acc2[cc][ww] += wa[cc] * hv[ww];
        }
#pragma unroll
        for (int cc = 0; cc < 8; ++cc) {
            float bb = sb2v[c0 + cc];
            float o[8];
#pragma unroll
            for (int ww = 0; ww < 8; ++ww) {
                o[ww] = acc2[cc][ww] + bb;
                s += o[ww];
                s2 += o[ww] * o[ww];
            }
            size_t gbase = (size_t)(b * 64 + c0 + cc) * 65536 + (size_t)h * 256;
            *(float4*)&g_z[gbase + wA] = make_float4(o[0], o[1], o[2], o[3]);
            *(float4*)&g_z[gbase + wB] = make_float4(o[4], o[5], o[6], o[7]);
        }
    }

    for (int off = 16; off > 0; off >>= 1) {
        s  += __shfl_down_sync(0xffffffffu, s,  off);
        s2 += __shfl_down_sync(0xffffffffu, s2, off);
    }
    int lane = tid & 31, widx = tid >> 5;
    if (lane == 0) { rbuf[widx] = s; rbuf[widx + 8] = s2; }
    __syncthreads();
    if (tid == 0) {
        float S = 0.0f, S2 = 0.0f;
        for (int i = 0; i < 8; ++i) { S += rbuf[i]; S2 += rbuf[i + 8]; }
        g_p2[blockIdx.x * 2] = S;
        g_p2[blockIdx.x * 2 + 1] = S2;
    }
}

__global__ void k_red2() {
    __shared__ float rbuf[16];
    int b = blockIdx.x, tid = threadIdx.x;
    float s  = g_p2[(b * 256 + tid) * 2];
    float s2 = g_p2[(b * 256 + tid) * 2 + 1];
    for (int off = 16; off > 0; off >>= 1) {
        s  += __shfl_down_sync(0xffffffffu, s,  off);
        s2 += __shfl_down_sync(0xffffffffu, s2, off);
    }
    int lane = tid & 31, wid = tid >> 5;
    if (lane == 0) { rbuf[wid] = s; rbuf[wid + 8] = s2; }
    __syncthreads();
    if (tid == 0) {
        float S = 0.0f, S2 = 0.0f;
        for (int i = 0; i < 8; ++i) { S += rbuf[i]; S2 += rbuf[i + 8]; }
        float mean = S * (1.0f / 4194304.0f);
        float var  = S2 * (1.0f / 4194304.0f) - mean * mean;
        g_s2[b * 2] = mean;
        g_s2[b * 2 + 1] = rsqrtf(var + 1e-5f);
    }
}

// ---- final: FiLM GN + skip2 ----
__global__ void k_final(const float* __restrict__ x, float* __restrict__ out) {
    int gi = blockIdx.x * 256 + threadIdx.x;
#pragma unroll
    for (int u = 0; u < 4; ++u) {
        size_t i4 = (size_t)gi + (size_t)u * 2097152;
        size_t e = i4 * 4;
        int b = (int)(e >> 22);
        int c = (int)((e >> 16) & 63);
        float mean = g_s2[b * 2], rstd = g_s2[b * 2 + 1];
        float ga = g_gb[(b * 64 + c) * 2], be = g_gb[(b * 64 + c) * 2 + 1];
        float4 zv = ((const float4*)g_z)[i4];
        float4 xv = ((const float4*)x)[i4];
        float4 ov;
        ov.x = ga * (zv.x - mean) * rstd + be + gelu_f(xv.x);
        ov.y = ga * (zv.y - mean) * rstd + be + gelu_f(xv.y);
        ov.z = ga * (zv.z - mean) * rstd + be + gelu_f(xv.z);
        ov.w = ga * (zv.w - mean) * rstd + be + gelu_f(xv.w);
        ((float4*)out)[i4] = ov;
    }
}

extern "C" void kernel_launch(void* const* d_in, const int* in_sizes, int n_in,
                              void* d_out, int out_size) {
    const float* x       = (const float*)d_in[0];
    const float* t       = (const float*)d_in[1];
    const float* w1r     = (const float*)d_in[2];
    const float* w1i     = (const float*)d_in[3];
    const float* w2r     = (const float*)d_in[4];
    const float* w2i     = (const float*)d_in[5];
    const float* norm1_w = (const float*)d_in[6];
    const float* norm1_b = (const float*)d_in[7];
    const float* mlp_w1  = (const float*)d_in[8];
    const float* mlp_b1  = (const float*)d_in[9];
    const float* mlp_w2  = (const float*)d_in[10];
    const float* mlp_b2  = (const float*)d_in[11];
    const float* gamma_w = (const float*)d_in[12];
    const float* gamma_b = (const float*)d_in[13];
    const float* beta_w  = (const float*)d_in[14];
    const float* beta_b  = (const float*)d_in[15];
    float* out = (float*)d_out;

    cudaFuncSetAttribute(k_fwdW, cudaFuncAttributeMaxDynamicSharedMemorySize, 65536);
    cudaFuncSetAttribute(k_fwdH, cudaFuncAttributeMaxDynamicSharedMemorySize, 67584);
    cudaFuncSetAttribute(k_mix,  cudaFuncAttributeMaxDynamicSharedMemorySize, 131072);
    cudaFuncSetAttribute(k_invW, cudaFuncAttributeMaxDynamicSharedMemorySize, 73728);
    cudaFuncSetAttribute(k_mlp,  cudaFuncAttributeMaxDynamicSharedMemorySize, 115584);

    k_tab<<<1, 256>>>();
    k_film<<<PB, PC>>>(t, gamma_w, gamma_b, beta_w, beta_b);
    k_fwdW<<<NROWS / 32, 256, 65536>>>(x);
    k_fwdH<<<PB * PC, 256, 67584>>>();
    k_mix<<<128, 1024, 131072>>>(w1r, w1i, w2r, w2i);
    k_invH<<<PB * PC, 256>>>();
    k_invW<<<PB * PC * 4, 256, 73728>>>();
    k_red1<<<PB, 256>>>();
    k_mlp<<<PB * PH, 256, 115584>>>(x, norm1_w, norm1_b,
                                    mlp_w1, mlp_b1, mlp_w2, mlp_b2);
    k_red2<<<PB, 256>>>();
    k_final<<<8192, 256>>>(x, out);
}

// round 8
// speedup vs baseline: 1.4354x; 1.0498x over previous
#include <cuda_runtime.h>
#include <math.h>

#define PB 8
#define PC 64
#define PH 256
#define PW 256
#define PKX 64
#define PKY 32
#define NROWS (PB*PC*PH)

// ---- scratch (device globals; no runtime allocation) ----
__device__ __align__(16) float  g_T[256*64];
__device__ __align__(16) float  g_cos[256];
__device__ __align__(16) float  g_sin[256];
__device__ __align__(16) float2 g_ct[256];            // (cos, sin) pairs
__device__ __align__(16) float2 g_X1[PB*PC*PH*PKY];   // after fwd-W  [b,c,h,ky]
__device__ __align__(16) float2 g_XF[PB*PC*PKX*PKY];  // after fwd-H  [b,c,kx',ky]
__device__ __align__(16) float2 g_OF[PB*PC*PKX*PKY];  // after mix
__device__ __align__(16) float2 g_Y1[PB*PC*PKY*PH];   // after inv-H  [b,c,ky,h]
__device__ __align__(16) float  g_y[PB*PC*PH*PW];     // spectral conv out
__device__ __align__(16) float  g_z[PB*PC*PH*PW];     // MLP out
__device__ __align__(16) float  g_p1[PB*PC*4*2];      // per-invW-block partials
__device__ __align__(16) float  g_p2[PB*PH*2];
__device__ __align__(16) float  g_s1[PB*2];
__device__ __align__(16) float  g_s2[PB*2];
__device__ __align__(16) float  g_gb[PB*PC*2];

__device__ __forceinline__ float gelu_f(float v) {
    return 0.5f * v * (1.0f + erff(v * 0.7071067811865476f));
}

// ---- twiddle tables ----
__global__ void k_tab() {
    int j = threadIdx.x;
    double sd, cd;
    sincospi((double)j * (2.0 / 256.0), &sd, &cd);
    g_cos[j] = (float)cd;
    g_sin[j] = (float)sd;
    g_ct[j] = make_float2((float)cd, (float)sd);
    for (int ky = 0; ky < 32; ++ky) {
        int idx = (ky * j) & 255;
        double s2, c2;
        sincospi((double)idx * (2.0 / 256.0), &s2, &c2);
        g_T[j * 64 + 2 * ky]     = (float)c2;
        g_T[j * 64 + 2 * ky + 1] = (float)(-s2);
    }
}

// ---- FiLM gamma/beta ----
__global__ void k_film(const float* __restrict__ t,
                       const float* __restrict__ gw, const float* __restrict__ gb,
                       const float* __restrict__ bw, const float* __restrict__ bb) {
    int b = blockIdx.x, o = threadIdx.x;
    float g = gb[o], be = bb[o];
    for (int c = 0; c < PC; ++c) {
        float tv = t[b * PC + c];
        g  += gw[o * PC + c] * tv;
        be += bw[o * PC + c] * tv;
    }
    g_gb[(b * PC + o) * 2]     = g;
    g_gb[(b * PC + o) * 2 + 1] = be;
}

// ---- forward DFT along W, radix-2; 64 rows/block, 2r x 8c thread tiles ----
__global__ void __launch_bounds__(256) k_fwdW(const float* __restrict__ x) {
    extern __shared__ char smraw[];
    float2* su = (float2*)smraw;            // [row 64][w<128] (u0,u1)  64KB
    float*  sT = (float*)(smraw + 65536);   // [w<128][64]              32KB
    int tid = threadIdx.x;
    size_t base = (size_t)blockIdx.x * 64 * 256;

    for (int i = tid; i < 2048; i += 256) {
        int row = i >> 5, w4 = (i & 31) * 4;
        float4 a = *(const float4*)&x[base + row * 256 + w4];
        float4 b = *(const float4*)&x[base + row * 256 + w4 + 128];
        float4* d = (float4*)&su[row * 128 + w4];
        d[0] = make_float4(a.x + b.x, a.x - b.x, a.y + b.y, a.y - b.y);
        d[1] = make_float4(a.z + b.z, a.z - b.z, a.w + b.w, a.w - b.w);
    }
    const float4* gT4 = (const float4*)g_T;
    float4* sT4 = (float4*)sT;
    for (int i = tid; i < 2048; i += 256) sT4[i] = gT4[i];   // rows 0..127
    __syncthreads();

    int r0 = (tid >> 3) * 2;       // 32 row groups x 2 rows
    int c0 = (tid & 7) * 8;        // 8 col groups x 8 cols

    float acc[2][8];
#pragma unroll
    for (int r = 0; r < 2; ++r)
#pragma unroll
        for (int u = 0; u < 8; ++u) acc[r][u] = 0.0f;

    const float2* rowA = su + r0 * 128;
    const float2* rowB = rowA + 128;
#pragma unroll 4
    for (int k = 0; k < 128; ++k) {
        float2 ua = rowA[k];
        float2 ub = rowB[k];
        float4 t0 = *(const float4*)&sT[k * 64 + c0];
        float4 t1 = *(const float4*)&sT[k * 64 + c0 + 4];
        // cols c0..c0+1: even ky -> u.x ; c0+2..3: odd ky -> u.y ; repeat
        acc[0][0] += ua.x * t0.x; acc[0][1] += ua.x * t0.y;
        acc[0][2] += ua.y * t0.z; acc[0][3] += ua.y * t0.w;
        acc[0][4] += ua.x * t1.x; acc[0][5] += ua.x * t1.y;
        acc[0][6] += ua.y * t1.z; acc[0][7] += ua.y * t1.w;
        acc[1][0] += ub.x * t0.x; acc[1][1] += ub.x * t0.y;
        acc[1][2] += ub.y * t0.z; acc[1][3] += ub.y * t0.w;
        acc[1][4] += ub.x * t1.x; acc[1][5] += ub.x * t1.y;
        acc[1][6] += ub.y * t1.z; acc[1][7] += ub.y * t1.w;
    }
    float* go = (float*)g_X1 + (size_t)blockIdx.x * 64 * 64;
#pragma unroll
    for (int r = 0; r < 2; ++r) {
        *(float4*)&go[(r0 + r) * 64 + c0] =
            make_float4(acc[r][0], acc[r][1], acc[r][2], acc[r][3]);
        *(float4*)&go[(r0 + r) * 64 + c0 + 4] =
            make_float4(acc[r][4], acc[r][5], acc[r][6], acc[r][7]);
    }
}

// ---- forward DFT along H, radix-2 over h, unroll-2 with hoisted loads ----
__global__ void __launch_bounds__(256) k_fwdH() {
    extern __shared__ char smraw[];
    float2* sv0 = (float2*)smraw;              // h<128, even-kx operand (sum)
    float2* sv1 = sv0 + 4096;                  // odd-kx operand (diff)
    float2* ct  = (float2*)(smraw + 65536);
    int tid = threadIdx.x, bc = blockIdx.x;

    const float4* src = (const float4*)(g_X1 + (size_t)bc * 8192);
    float4* d0 = (float4*)sv0;
    float4* d1 = (float4*)sv1;
    for (int i = tid; i < 2048; i += 256) {
        float4 a = src[i];
        float4 b = src[i + 2048];               // h+128
        d0[i] = make_float4(a.x + b.x, a.y + b.y, a.z + b.z, a.w + b.w);
        d1[i] = make_float4(a.x - b.x, a.y - b.y, a.z - b.z, a.w - b.w);
    }
    ct[tid] = g_ct[tid];
    __syncthreads();

    int kxp0 = (tid >> 3) * 2;                 // even
    int ky0  = (tid & 7) * 4;
    int kxm0 = kxp0 + ((kxp0 >= 32) ? 192 : 0);  // even
    int kxm1 = kxm0 + 1;                          // odd

    float2 a0[4], a1[4];
#pragma unroll
    for (int j = 0; j < 4; ++j) {
        a0[j] = make_float2(0.f, 0.f);
        a1[j] = make_float2(0.f, 0.f);
    }

    int i0 = 0, i1 = 0;
    int s0 = (2 * kxm0) & 255, s1 = (2 * kxm1) & 255;
    for (int h = 0; h < 128; h += 2) {
        float2 e00 = ct[i0];
        float2 e01 = ct[(i0 + kxm0) & 255];
        float2 e10 = ct[i1];
        float2 e11 = ct[(i1 + kxm1) & 255];
        i0 = (i0 + s0) & 255;
        i1 = (i1 + s1) & 255;
        float4 xA0 = *(const float4*)&sv0[h * 32 + ky0];
        float4 xB0 = *(const float4*)&sv0[h * 32 + ky0 + 2];
        float4 xA1 = *(const float4*)&sv1[h * 32 + ky0];
        float4 xB1 = *(const float4*)&sv1[h * 32 + ky0 + 2];
        float4 yA0 = *(const float4*)&sv0[(h + 1) * 32 + ky0];
        float4 yB0 = *(const float4*)&sv0[(h + 1) * 32 + ky0 + 2];
        float4 yA1 = *(const float4*)&sv1[(h + 1) * 32 + ky0];
        float4 yB1 = *(const float4*)&sv1[(h + 1) * 32 + ky0 + 2];

        float2 v0[4] = { {xA0.x, xA0.y}, {xA0.z, xA0.w}, {xB0.x, xB0.y}, {xB0.z, xB0.w} };
        float2 v1[4] = { {xA1.x, xA1.y}, {xA1.z, xA1.w}, {xB1.x, xB1.y}, {xB1.z, xB1.w} };
#pragma unroll
        for (int j = 0; j < 4; ++j) {
            a0[j].x += v0[j].x * e00.x + v0[j].y * e00.y;
            a0[j].y += v0[j].y * e00.x - v0[j].x * e00.y;
            a1[j].x += v1[j].x * e10.x + v1[j].y * e10.y;
            a1[j].y += v1[j].y * e10.x - v1[j].x * e10.y;
        }
        float2 w0[4] = { {yA0.x, yA0.y}, {yA0.z, yA0.w}, {yB0.x, yB0.y}, {yB0.z, yB0.w} };
        float2 w1[4] = { {yA1.x, yA1.y}, {yA1.z, yA1.w}, {yB1.x, yB1.y}, {yB1.z, yB1.w} };
#pragma unroll
        for (int j = 0; j < 4; ++j) {
            a0[j].x += w0[j].x * e01.x + w0[j].y * e01.y;
            a0[j].y += w0[j].y * e01.x - w0[j].x * e01.y;
            a1[j].x += w1[j].x * e11.x + w1[j].y * e11.y;
            a1[j].y += w1[j].y * e11.x - w1[j].x * e11.y;
        }
    }
    float2* o0 = g_XF + ((size_t)bc * 64 + kxp0) * 32 + ky0;
    float2* o1 = o0 + 32;
    *(float4*)&o0[0] = make_float4(a0[0].x, a0[0].y, a0[1].x, a0[1].y);
    *(float4*)&o0[2] = make_float4(a0[2].x, a0[2].y, a0[3].x, a0[3].y);
    *(float4*)&o1[0] = make_float4(a1[0].x, a1[0].y, a1[1].x, a1[1].y);
    *(float4*)&o1[2] = make_float4(a1[2].x, a1[2].y, a1[3].x, a1[3].y);
}

// ---- per-mode complex channel mixing ----
__global__ void __launch_bounds__(1024, 1)
k_mix(const float* __restrict__ w1r, const float* __restrict__ w1i,
      const float* __restrict__ w2r, const float* __restrict__ w2i) {
    extern __shared__ char smraw[];
    float2* sXF = (float2*)smraw;   // [(b*64+i)*32+ky], 16384 float2
    int kxp = blockIdx.x >> 1, half = blockIdx.x & 1;
    int tid = threadIdx.x;

    for (int i = tid; i < 16384; i += 1024) {
        int b = i >> 11, rest = i & 2047, ii = rest >> 5, kk = rest & 31;
        sXF[i] = g_XF[(((size_t)b * PC + ii) * PKX + kxp) * PKY + kk];
    }
    __syncthreads();

    int o = half * 32 + (tid >> 5), ky = tid & 31;
    const float* wr; const float* wi; int kxl;
    if (kxp < 32) { wr = w1r; wi = w1i; kxl = kxp; }
    else          { wr = w2r; wi = w2i; kxl = kxp - 32; }

    float ar[8], ai[8];
#pragma unroll
    for (int b = 0; b < 8; ++b) { ar[b] = 0.0f; ai[b] = 0.0f; }

    for (int i = 0; i < 64; ++i) {
        size_t widx = (((size_t)i * PC + o) * 32 + kxl) * 32 + ky;
        float wrv = wr[widx], wiv = wi[widx];
#pragma unroll
        for (int b = 0; b < 8; ++b) {
            float2 v = sXF[(b * 64 + i) * 32 + ky];
            ar[b] += v.x * wrv - v.y * wiv;
            ai[b] += v.x * wiv + v.y * wrv;
        }
    }
#pragma unroll
    for (int b = 0; b < 8; ++b)
        g_OF[(((size_t)b * PC + o) * PKX + kxp) * PKY + ky] = make_float2(ar[b], ai[b]);
}

// ---- inverse DFT along H, radix-2: Se/So over kx parity, emit h and h+128 ----
__global__ void __launch_bounds__(256) k_invH() {
    __shared__ float2 sOF[2048];
    __shared__ float2 ct[256];
    int tid = threadIdx.x, bc = blockIdx.x;

    const float4* src = (const float4*)(g_OF + (size_t)bc * 2048);
    float4* dst = (float4*)sOF;
    for (int i = tid; i < 1024; i += 256) dst[i] = src[i];
    ct[tid] = g_ct[tid];
    __syncthreads();

    int h0  = (tid >> 3) * 4;     // h<128
    int ky0 = (tid & 7) * 4;

    float2 ae[4][4], ao[4][4];
#pragma unroll
    for (int hh = 0; hh < 4; ++hh)
#pragma unroll
        for (int j = 0; j < 4; ++j) {
            ae[hh][j] = make_float2(0.f, 0.f);
            ao[hh][j] = make_float2(0.f, 0.f);
        }

    for (int kxp = 0; kxp < 64; kxp += 2) {
        int kxm = kxp + ((kxp >= 32) ? 192 : 0);   // even
        float2 te[4], to[4];
#pragma unroll
        for (int hh = 0; hh < 4; ++hh) {
            int h = h0 + hh;
            te[hh] = ct[(kxm * h) & 255];
            to[hh] = ct[((kxm + 1) * h) & 255];
        }
        float4 eA = *(const float4*)&sOF[kxp * 32 + ky0];
        float4 eB = *(const float4*)&sOF[kxp * 32 + ky0 + 2];
        float4 oA = *(const float4*)&sOF[(kxp + 1) * 32 + ky0];
        float4 oB = *(const float4*)&sOF[(kxp + 1) * 32 + ky0 + 2];
        float2 ove[4] = { {eA.x, eA.y}, {eA.z, eA.w}, {eB.x, eB.y}, {eB.z, eB.w} };
        float2 ovo[4] = { {oA.x, oA.y}, {oA.z, oA.w}, {oB.x, oB.y}, {oB.z, oB.w} };
#pragma unroll
        for (int hh = 0; hh < 4; ++hh) {
#pragma unroll
            for (int j = 0; j < 4; ++j) {
                ae[hh][j].x += ove[j].x * te[hh].x - ove[j].y * te[hh].y;
                ae[hh][j].y += ove[j].x * te[hh].y + ove[j].y * te[hh].x;
                ao[hh][j].x += ovo[j].x * to[hh].x - ovo[j].y * to[hh].y;
                ao[hh][j].y += ovo[j].x * to[hh].y + ovo[j].y * to[hh].x;
            }
        }
    }
#pragma unroll
    for (int j = 0; j < 4; ++j) {
        float2* out = g_Y1 + (size_t)bc * 8192 + (ky0 + j) * 256 + h0;
#pragma unroll
        for (int hh = 0; hh < 4; hh += 2) {
            *(float4*)&out[hh] = make_float4(
                ae[hh][j].x + ao[hh][j].x,     ae[hh][j].y + ao[hh][j].y,
                ae[hh+1][j].x + ao[hh+1][j].x, ae[hh+1][j].y + ao[hh+1][j].y);
            *(float4*)&out[hh + 128] = make_float4(
                ae[hh][j].x - ao[hh][j].x,     ae[hh][j].y - ao[hh][j].y,
                ae[hh+1][j].x - ao[hh+1][j].x, ae[hh+1][j].y - ao[hh+1][j].y);
        }
    }
}

// ---- inverse rfft along W, radix-2: Se/So over ky parity, emit w and w+128 ----
__global__ void __launch_bounds__(256) k_invW() {
    extern __shared__ char smraw[];
    float2* sY = (float2*)smraw;               // 8192 float2 (64KB)
    float2* sW = (float2*)(smraw + 65536);     // 31*32 float2
    __shared__ float rbuf[16];
    int tid = threadIdx.x;
    int bc = blockIdx.x >> 2, wt = blockIdx.x & 3;
    int w0 = wt * 32;                           // outputs w0.. and w0+128..

    const float4* src = (const float4*)(g_Y1 + (size_t)bc * 8192);
    float4* dst = (float4*)sY;
    for (int i = tid; i < 4096; i += 256) dst[i] = src[i];

    const float inv = 1.0f / 65536.0f;
    for (int i = tid; i < 31 * 32; i += 256) {
        int ky = (i >> 5) + 1;
        int w  = w0 + (i & 31);
        int idx = (ky * w) & 255;
        sW[i] = make_float2(2.0f * inv * g_cos[idx], 2.0f * inv * g_sin[idx]);
    }
    __syncthreads();

    int h0  = (tid >> 3) * 8;
    int wth = (tid & 7) * 4;

    float se[8][4], so[8][4], dc[8];
#pragma unroll
    for (int hh = 0; hh < 8; ++hh) {
        dc[hh] = inv * sY[h0 + hh].x;
#pragma unroll
        for (int ww = 0; ww < 4; ++ww) { se[hh][ww] = 0.f; so[hh][ww] = 0.f; }
    }

    for (int ky = 1; ky < 31; ky += 2) {
        {   // odd ky -> so
            float2 av[8], bv[4];
            const float4* ap = (const float4*)&sY[ky * 256 + h0];
#pragma unroll
            for (int u = 0; u < 4; ++u) {
                float4 t1 = ap[u];
                av[2*u] = make_float2(t1.x, t1.y);
                av[2*u+1] = make_float2(t1.z, t1.w);
            }
            const float4* bp = (const float4*)&sW[(ky - 1) * 32 + wth];
            float4 t2 = bp[0], t3 = bp[1];
            bv[0] = make_float2(t2.x, t2.y); bv[1] = make_float2(t2.z, t2.w);
            bv[2] = make_float2(t3.x, t3.y); bv[3] = make_float2(t3.z, t3.w);
#pragma unroll
            for (int hh = 0; hh < 8; ++hh)
#pragma unroll
                for (int ww = 0; ww < 4; ++ww)
                    so[hh][ww] += av[hh].x * bv[ww].x - av[hh].y * bv[ww].y;
        }
        {   // even ky+1 -> se
            float2 av[8], bv[4];
            const float4* ap = (const float4*)&sY[(ky + 1) * 256 + h0];
#pragma unroll
            for (int u = 0; u < 4; ++u) {
                float4 t1 = ap[u];
                av[2*u] = make_float2(t1.x, t1.y);
                av[2*u+1] = make_float2(t1.z, t1.w);
            }
            const float4* bp = (const float4*)&sW[ky * 32 + wth];
            float4 t2 = bp[0], t3 = bp[1];
            bv[0] = make_float2(t2.x, t2.y); bv[1] = make_float2(t2.z, t2.w);
            bv[2] = make_float2(t3.x, t3.y); bv[3] = make_float2(t3.z, t3.w);
#pragma unroll
            for (int hh = 0; hh < 8; ++hh)
#pragma unroll
                for (int ww = 0; ww < 4; ++ww)
                    se[hh][ww] += av[hh].x * bv[ww].x - av[hh].y * bv[ww].y;
        }
    }
    {   // ky = 31 (odd) -> so
        float2 av[8], bv[4];
        const float4* ap = (const float4*)&sY[31 * 256 + h0];
#pragma unroll
        for (int u = 0; u < 4; ++u) {
            float4 t1 = ap[u];
            av[2*u] = make_float2(t1.x, t1.y);
            av[2*u+1] = make_float2(t1.z, t1.w);
        }
        const float4* bp = (const float4*)&sW[30 * 32 + wth];
        float4 t2 = bp[0], t3 = bp[1];
        bv[0] = make_float2(t2.x, t2.y); bv[1] = make_float2(t2.z, t2.w);
        bv[2] = make_float2(t3.x, t3.y); bv[3] = make_float2(t3.z, t3.w);
#pragma unroll
        for (int hh = 0; hh < 8; ++hh)
#pragma unroll
            for (int ww = 0; ww < 4; ++ww)
                so[hh][ww] += av[hh].x * bv[ww].x - av[hh].y * bv[ww].y;
    }

    float s = 0.0f, s2 = 0.0f;
#pragma unroll
    for (int hh = 0; hh < 8; ++hh) {
        float lo[4], hi[4];
#pragma unroll
        for (int ww = 0; ww < 4; ++ww) {
            lo[ww] = dc[hh] + se[hh][ww] + so[hh][ww];
            hi[ww] = dc[hh] + se[hh][ww] - so[hh][ww];
            s += lo[ww] + hi[ww];
            s2 += lo[ww] * lo[ww] + hi[ww] * hi[ww];
        }
        size_t base = (size_t)bc * 65536 + (size_t)(h0 + hh) * 256 + w0 + wth;
        *(float4*)&g_y[base]       = make_float4(lo[0], lo[1], lo[2], lo[3]);
        *(float4*)&g_y[base + 128] = make_float4(hi[0], hi[1], hi[2], hi[3]);
    }

    for (int off = 16; off > 0; off >>= 1) {
        s  += __shfl_down_sync(0xffffffffu, s,  off);
        s2 += __shfl_down_sync(0xffffffffu, s2, off);
    }
    int lane = tid & 31, wid = tid >> 5;
    if (lane == 0) { rbuf[wid] = s; rbuf[wid + 8] = s2; }
    __syncthreads();
    if (tid == 0) {
        float S = 0.0f, S2 = 0.0f;
        for (int i = 0; i < 8; ++i) { S += rbuf[i]; S2 += rbuf[i + 8]; }
        g_p1[blockIdx.x * 2] = S;
        g_p1[blockIdx.x * 2 + 1] = S2;
    }
}

__global__ void k_red1() {
    __shared__ float rbuf[16];
    int b = blockIdx.x, tid = threadIdx.x;   // 256 partials per b
    float s  = g_p1[(b * 256 + tid) * 2];
    float s2 = g_p1[(b * 256 + tid) * 2 + 1];
    for (int off = 16; off > 0; off >>= 1) {
        s  += __shfl_down_sync(0xffffffffu, s,  off);
        s2 += __shfl_down_sync(0xffffffffu, s2, off);
    }
    int lane = tid & 31, wid = tid >> 5;
    if (lane == 0) { rbuf[wid] = s; rbuf[wid + 8] = s2; }
    __syncthreads();
    if (tid == 0) {
        float S = 0.0f, S2 = 0.0f;
        for (int i = 0; i < 8; ++i) { S += rbuf[i]; S2 += rbuf[i + 8]; }
        float mean = S * (1.0f / 4194304.0f);
        float var  = S2 * (1.0f / 4194304.0f) - mean * mean;
        g_s1[b * 2] = mean;
        g_s1[b * 2 + 1] = rsqrtf(var + 1e-5f);
    }
}

// ---- GN1 apply + residual + gelu + MLP + GN2 partials (W split in halves) ----
__global__ void __launch_bounds__(256) k_mlp(const float* __restrict__ x,
                      const float* __restrict__ nw, const float* __restrict__ nb,
                      const float* __restrict__ w1, const float* __restrict__ b1,
                      const float* __restrict__ w2, const float* __restrict__ b2) {
    extern __shared__ char smraw[];
    float* sy2  = (float*)smraw;        // [c][w]  64*128
    float* sh   = sy2 + 8192;           // [m][w]  32*128
    float* sw1  = sh + 4096;            // [c][m]  64*32
    float* sw2  = sw1 + 2048;           // [m][c]  32*64
    float* sb1  = sw2 + 2048;           // 32
    float* sb2v = sb1 + 32;             // 64
    float* snw  = sb2v + 64;            // 64
    float* snb  = snw + 64;             // 64
    __shared__ float rbuf[16];

    int tid = threadIdx.x;
    int b = blockIdx.x >> 8, h = blockIdx.x & 255;

    for (int i = tid; i < 2048; i += 256) {
        int c = i >> 5, m = i & 31;
        sw1[i] = w1[m * 64 + c];
        int m2 = i >> 6, c2 = i & 63;
        sw2[i] = w2[c2 * 32 + m2];
    }
    if (tid < 64) {
        sb2v[tid] = b2[tid];
        snw[tid] = nw[tid];
        snb[tid] = nb[tid];
        if (tid < 32) sb1[tid] = b1[tid];
    }
    float mean1 = g_s1[b * 2], rstd1 = g_s1[b * 2 + 1];
    __syncthreads();

    int m0 = (tid >> 5) * 4;      // layer1 m group
    int c0 = (tid >> 5) * 8;      // layer2 c group
    int wl = (tid & 31) * 4;      // w within half

    float s = 0.0f, s2 = 0.0f;
    for (int half = 0; half < 2; ++half) {
        int wbase = half * 128;

        // Phase A: y2 = gelu( gn1(y)*nw + nb + x )
        for (int i = tid; i < 2048; i += 256) {   // float4 units
            int c = i >> 5, w4 = (i & 31) * 4;
            size_t gid = (size_t)(b * 64 + c) * 65536 + (size_t)h * 256 + wbase + w4;
            float4 yv = *(const float4*)&g_y[gid];
            float4 xv = *(const float4*)&x[gid];
            float a = snw[c] * rstd1, bb = snb[c] - mean1 * rstd1 * snw[c];
            float4 o;
            o.x = gelu_f(yv.x * a + bb + xv.x);
            o.y = gelu_f(yv.y * a + bb + xv.y);
            o.z = gelu_f(yv.z * a + bb + xv.z);
            o.w = gelu_f(yv.w * a + bb + xv.w);
            *(float4*)&sy2[c * 128 + w4] = o;
        }
        __syncthreads();

        // Layer 1: h = gelu(W1 @ y2 + b1)   (32x64 @ 64x128)
        {
            float acc[4][4];
#pragma unroll
            for (int mm = 0; mm < 4; ++mm)
#pragma unroll
                for (int ww = 0; ww < 4; ++ww) acc[mm][ww] = 0.0f;
            for (int c = 0; c < 64; ++c) {
                float4 wv = *(const float4*)&sw1[c * 32 + m0];
                float4 yv = *(const float4*)&sy2[c * 128 + wl];
                float wa[4] = { wv.x, wv.y, wv.z, wv.w };
                float yy[4] = { yv.x, yv.y, yv.z, yv.w };
#pragma unroll
                for (int mm = 0; mm < 4; ++mm)
#pragma unroll
                    for (int ww = 0; ww < 4; ++ww) acc[mm][ww] += wa[mm] * yy[ww];
            }
#pragma unroll
            for (int mm = 0; mm < 4; ++mm) {
                float bb = sb1[m0 + mm];
                float4 o;
                o.x = gelu_f(acc[mm][0] + bb);
                o.y = gelu_f(acc[mm][1] + bb);
                o.z = gelu_f(acc[mm][2] + bb);
                o.w = gelu_f(acc[mm][3] + bb);
                *(float4*)&sh[(m0 + mm) * 128 + wl] = o;
            }
        }
        __syncthreads();

        // Layer 2: y3 = W2 @ h + b2   (64x32 @ 32x128) + GN2 partial stats
        {
            float acc2[8][4];
#pragma unroll
            for (int cc = 0; cc < 8; ++cc)
#pragma unroll
                for (int ww = 0; ww < 4; ++ww) acc2[cc][ww] = 0.0f;
            for (int m = 0; m < 32; ++m) {
                float4 a0 = *(const float4*)&sw2[m * 64 + c0];
                float4 a1 = *(const float4*)&sw2[m * 64 + c0 + 4];
                float4 hv = *(const float4*)&sh[m * 128 + wl];
                float wa[8] = { a0.x, a0.y, a0.z, a0.w, a1.x, a1.y, a1.z, a1.w };
                float hh[4] = { hv.x, hv.y, hv.z, hv.w };
#pragma unroll
                for (int cc = 0; cc < 8; ++cc)
#pragma unroll
                    for (int ww = 0; ww < 4; ++ww) acc2[cc][ww] += wa[cc] * hh[ww];
            }
#pragma unroll
            for (int cc = 0; cc < 8; ++cc) {
                float bb = sb2v[c0 + cc];
                float o[4];
#pragma unroll
                for (int ww = 0; ww < 4; ++ww) {
                    o[ww] = acc2[cc][ww] + bb;
                    s += o[ww];
                    s2 += o[ww] * o[ww];
                }
                size_t gbase = (size_t)(b * 64 + c0 + cc) * 65536 + (size_t)h * 256 + wbase;
                *(float4*)&g_z[gbase + wl] = make_float4(o[0], o[1], o[2], o[3]);
            }
        }
        __syncthreads();
    }

    for (int off = 16; off > 0; off >>= 1) {
        s  += __shfl_down_sync(0xffffffffu, s,  off);
        s2 += __shfl_down_sync(0xffffffffu, s2, off);
    }
    int lane = tid & 31, widx = tid >> 5;
    if (lane == 0) { rbuf[widx] = s; rbuf[widx + 8] = s2; }
    __syncthreads();
    if (tid == 0) {
        float S = 0.0f, S2 = 0.0f;
        for (int i = 0; i < 8; ++i) { S += rbuf[i]; S2 += rbuf[i + 8]; }
        g_p2[blockIdx.x * 2] = S;
        g_p2[blockIdx.x * 2 + 1] = S2;
    }
}

__global__ void k_red2() {
    __shared__ float rbuf[16];
    int b = blockIdx.x, tid = threadIdx.x;
    float s  = g_p2[(b * 256 + tid) * 2];
    float s2 = g_p2[(b * 256 + tid) * 2 + 1];
    for (int off = 16; off > 0; off >>= 1) {
        s  += __shfl_down_sync(0xffffffffu, s,  off);
        s2 += __shfl_down_sync(0xffffffffu, s2, off);
    }
    int lane = tid & 31, wid = tid >> 5;
    if (lane == 0) { rbuf[wid] = s; rbuf[wid + 8] = s2; }
    __syncthreads();
    if (tid == 0) {
        float S = 0.0f, S2 = 0.0f;
        for (int i = 0; i < 8; ++i) { S += rbuf[i]; S2 += rbuf[i + 8]; }
        float mean = S * (1.0f / 4194304.0f);
        float var  = S2 * (1.0f / 4194304.0f) - mean * mean;
        g_s2[b * 2] = mean;
        g_s2[b * 2 + 1] = rsqrtf(var + 1e-5f);
    }
}

// ---- final: FiLM GN + skip2 ----
__global__ void k_final(const float* __restrict__ x, float* __restrict__ out) {
    int gi = blockIdx.x * 256 + threadIdx.x;
#pragma unroll
    for (int u = 0; u < 4; ++u) {
        size_t i4 = (size_t)gi + (size_t)u * 2097152;
        size_t e = i4 * 4;
        int b = (int)(e >> 22);
        int c = (int)((e >> 16) & 63);
        float mean = g_s2[b * 2], rstd = g_s2[b * 2 + 1];
        float ga = g_gb[(b * 64 + c) * 2], be = g_gb[(b * 64 + c) * 2 + 1];
        float4 zv = ((const float4*)g_z)[i4];
        float4 xv = ((const float4*)x)[i4];
        float4 ov;
        ov.x = ga * (zv.x - mean) * rstd + be + gelu_f(xv.x);
        ov.y = ga * (zv.y - mean) * rstd + be + gelu_f(xv.y);
        ov.z = ga * (zv.z - mean) * rstd + be + gelu_f(xv.z);
        ov.w = ga * (zv.w - mean) * rstd + be + gelu_f(xv.w);
        ((float4*)out)[i4] = ov;
    }
}

extern "C" void kernel_launch(void* const* d_in, const int* in_sizes, int n_in,
                              void* d_out, int out_size) {
    const float* x       = (const float*)d_in[0];
    const float* t       = (const float*)d_in[1];
    const float* w1r     = (const float*)d_in[2];
    const float* w1i     = (const float*)d_in[3];
    const float* w2r     = (const float*)d_in[4];
    const float* w2i     = (const float*)d_in[5];
    const float* norm1_w = (const float*)d_in[6];
    const float* norm1_b = (const float*)d_in[7];
    const float* mlp_w1  = (const float*)d_in[8];
    const float* mlp_b1  = (const float*)d_in[9];
    const float* mlp_w2  = (const float*)d_in[10];
    const float* mlp_b2  = (const float*)d_in[11];
    const float* gamma_w = (const float*)d_in[12];
    const float* gamma_b = (const float*)d_in[13];
    const float* beta_w  = (const float*)d_in[14];
    const float* beta_b  = (const float*)d_in[15];
    float* out = (float*)d_out;

    cudaFuncSetAttribute(k_fwdW, cudaFuncAttributeMaxDynamicSharedMemorySize, 98304);
    cudaFuncSetAttribute(k_fwdH, cudaFuncAttributeMaxDynamicSharedMemorySize, 67584);
    cudaFuncSetAttribute(k_mix,  cudaFuncAttributeMaxDynamicSharedMemorySize, 131072);
    cudaFuncSetAttribute(k_invW, cudaFuncAttributeMaxDynamicSharedMemorySize, 73728);
    cudaFuncSetAttribute(k_mlp,  cudaFuncAttributeMaxDynamicSharedMemorySize, 66432);

    k_tab<<<1, 256>>>();
    k_film<<<PB, PC>>>(t, gamma_w, gamma_b, beta_w, beta_b);
    k_fwdW<<<NROWS / 64, 256, 98304>>>(x);
    k_fwdH<<<PB * PC, 256, 67584>>>();
    k_mix<<<128, 1024, 131072>>>(w1r, w1i, w2r, w2i);
    k_invH<<<PB * PC, 256>>>();
    k_invW<<<PB * PC * 4, 256, 73728>>>();
    k_red1<<<PB, 256>>>();
    k_mlp<<<PB * PH, 256, 66432>>>(x, norm1_w, norm1_b,
                                   mlp_w1, mlp_b1, mlp_w2, mlp_b2);
    k_red2<<<PB, 256>>>();
    k_final<<<8192, 256>>>(x, out);
}

// round 9
// speedup vs baseline: 1.5114x; 1.0529x over previous
#include <cuda_runtime.h>
#include <math.h>

#define PB 8
#define PC 64
#define PH 256
#define PW 256
#define PKX 64
#define PKY 32
#define NROWS (PB*PC*PH)

// ---- scratch (device globals; no runtime allocation) ----
__device__ __align__(16) float  g_T[256*64];
__device__ __align__(16) float  g_cos[256];
__device__ __align__(16) float  g_sin[256];
__device__ __align__(16) float2 g_ct[256];            // (cos, sin) pairs
__device__ __align__(16) float2 g_X1[PB*PC*PH*PKY];   // after fwd-W  [b,c,h,ky]
__device__ __align__(16) float2 g_XF[PB*PC*PKX*PKY];  // after fwd-H  [b,c,kx',ky]
__device__ __align__(16) float2 g_OF[PB*PC*PKX*PKY];  // after mix
__device__ __align__(16) float2 g_Y1[PB*PC*PKY*PH];   // after inv-H  [b,c,ky,h]
__device__ __align__(16) float  g_y[PB*PC*PH*PW];     // spectral conv out
__device__ __align__(16) float  g_z[PB*PC*PH*PW];     // MLP out
__device__ __align__(16) float  g_p1[PB*PC*4*2];      // per-invW-block partials
__device__ __align__(16) float  g_p2[PB*PH*2];
__device__ __align__(16) float  g_s1[PB*2];
__device__ __align__(16) float  g_s2[PB*2];
__device__ __align__(16) float  g_gb[PB*PC*2];

__device__ __forceinline__ float gelu_f(float v) {
    return 0.5f * v * (1.0f + erff(v * 0.7071067811865476f));
}

// ---- twiddle tables ----
__global__ void k_tab() {
    int j = threadIdx.x;
    double sd, cd;
    sincospi((double)j * (2.0 / 256.0), &sd, &cd);
    g_cos[j] = (float)cd;
    g_sin[j] = (float)sd;
    g_ct[j] = make_float2((float)cd, (float)sd);
    for (int ky = 0; ky < 32; ++ky) {
        int idx = (ky * j) & 255;
        double s2, c2;
        sincospi((double)idx * (2.0 / 256.0), &s2, &c2);
        g_T[j * 64 + 2 * ky]     = (float)c2;
        g_T[j * 64 + 2 * ky + 1] = (float)(-s2);
    }
}

// ---- FiLM gamma/beta ----
__global__ void k_film(const float* __restrict__ t,
                       const float* __restrict__ gw, const float* __restrict__ gb,
                       const float* __restrict__ bw, const float* __restrict__ bb) {
    int b = blockIdx.x, o = threadIdx.x;
    float g = gb[o], be = bb[o];
    for (int c = 0; c < PC; ++c) {
        float tv = t[b * PC + c];
        g  += gw[o * PC + c] * tv;
        be += bw[o * PC + c] * tv;
    }
    g_gb[(b * PC + o) * 2]     = g;
    g_gb[(b * PC + o) * 2 + 1] = be;
}

// ---- forward DFT along W, radix-2; 64 rows/block, 2r x 8c thread tiles ----
__global__ void __launch_bounds__(256) k_fwdW(const float* __restrict__ x) {
    extern __shared__ char smraw[];
    float2* su = (float2*)smraw;            // [row 64][w<128] (u0,u1)  64KB
    float*  sT = (float*)(smraw + 65536);   // [w<128][64]              32KB
    int tid = threadIdx.x;
    size_t base = (size_t)blockIdx.x * 64 * 256;

    for (int i = tid; i < 2048; i += 256) {
        int row = i >> 5, w4 = (i & 31) * 4;
        float4 a = *(const float4*)&x[base + row * 256 + w4];
        float4 b = *(const float4*)&x[base + row * 256 + w4 + 128];
        float4* d = (float4*)&su[row * 128 + w4];
        d[0] = make_float4(a.x + b.x, a.x - b.x, a.y + b.y, a.y - b.y);
        d[1] = make_float4(a.z + b.z, a.z - b.z, a.w + b.w, a.w - b.w);
    }
    const float4* gT4 = (const float4*)g_T;
    float4* sT4 = (float4*)sT;
    for (int i = tid; i < 2048; i += 256) sT4[i] = gT4[i];   // rows 0..127
    __syncthreads();

    int r0 = (tid >> 3) * 2;       // 32 row groups x 2 rows
    int c0 = (tid & 7) * 8;        // 8 col groups x 8 cols

    float acc[2][8];
#pragma unroll
    for (int r = 0; r < 2; ++r)
#pragma unroll
        for (int u = 0; u < 8; ++u) acc[r][u] = 0.0f;

    const float2* rowA = su + r0 * 128;
    const float2* rowB = rowA + 128;
#pragma unroll 4
    for (int k = 0; k < 128; ++k) {
        float2 ua = rowA[k];
        float2 ub = rowB[k];
        float4 t0 = *(const float4*)&sT[k * 64 + c0];
        float4 t1 = *(const float4*)&sT[k * 64 + c0 + 4];
        acc[0][0] += ua.x * t0.x; acc[0][1] += ua.x * t0.y;
        acc[0][2] += ua.y * t0.z; acc[0][3] += ua.y * t0.w;
        acc[0][4] += ua.x * t1.x; acc[0][5] += ua.x * t1.y;
        acc[0][6] += ua.y * t1.z; acc[0][7] += ua.y * t1.w;
        acc[1][0] += ub.x * t0.x; acc[1][1] += ub.x * t0.y;
        acc[1][2] += ub.y * t0.z; acc[1][3] += ub.y * t0.w;
        acc[1][4] += ub.x * t1.x; acc[1][5] += ub.x * t1.y;
        acc[1][6] += ub.y * t1.z; acc[1][7] += ub.y * t1.w;
    }
    float* go = (float*)g_X1 + (size_t)blockIdx.x * 64 * 64;
#pragma unroll
    for (int r = 0; r < 2; ++r) {
        *(float4*)&go[(r0 + r) * 64 + c0] =
            make_float4(acc[r][0], acc[r][1], acc[r][2], acc[r][3]);
        *(float4*)&go[(r0 + r) * 64 + c0 + 4] =
            make_float4(acc[r][4], acc[r][5], acc[r][6], acc[r][7]);
    }
}

// ---- forward DFT along H, radix-2 over h, ky-split for occupancy ----
__global__ void __launch_bounds__(256) k_fwdH() {
    extern __shared__ char smraw[];
    float2* sv0 = (float2*)smraw;              // [h<128][16 ky] even-kx operand (sum)
    float2* sv1 = sv0 + 2048;                  // odd-kx operand (diff)
    float2* ct  = (float2*)(smraw + 32768);    // 256 twiddles
    int tid = threadIdx.x;
    int bc = blockIdx.x >> 1, kh = blockIdx.x & 1;

    const float4* src = (const float4*)(g_X1 + (size_t)bc * 8192);
    float4* d0 = (float4*)sv0;
    float4* d1 = (float4*)sv1;
    for (int i = tid; i < 1024; i += 256) {
        int h = i >> 3, j = i & 7;
        int s = h * 16 + kh * 8 + j;
        float4 a = src[s];
        float4 b = src[s + 2048];      // h+128
        d0[i] = make_float4(a.x + b.x, a.y + b.y, a.z + b.z, a.w + b.w);
        d1[i] = make_float4(a.x - b.x, a.y - b.y, a.z - b.z, a.w - b.w);
    }
    ct[tid] = g_ct[tid];
    __syncthreads();

    int p   = tid >> 3;                // kx pair 0..31
    int kyl = (tid & 7) * 2;           // local ky 0..14 step 2
    int kxe = 2 * p;
    int kxm_e = kxe + ((kxe >= 32) ? 192 : 0);
    int kxm_o = kxm_e + 1;

    float2 ae[2] = {{0.f,0.f},{0.f,0.f}};
    float2 ao[2] = {{0.f,0.f},{0.f,0.f}};

    int ie = 0, io = 0;
    int se2 = (2 * kxm_e) & 255, so2 = (2 * kxm_o) & 255;
#pragma unroll 2
    for (int h = 0; h < 128; h += 2) {
        float2 e0 = ct[ie];
        float2 e1 = ct[(ie + kxm_e) & 255];
        float2 f0 = ct[io];
        float2 f1 = ct[(io + kxm_o) & 255];
        ie = (ie + se2) & 255;
        io = (io + so2) & 255;
        float4 x0 = *(const float4*)&sv0[h * 16 + kyl];
        float4 x1 = *(const float4*)&sv1[h * 16 + kyl];
        float4 y0 = *(const float4*)&sv0[(h + 1) * 16 + kyl];
        float4 y1 = *(const float4*)&sv1[(h + 1) * 16 + kyl];
        // even kx (sum operand): (xr + i xi)(c - i s)
        ae[0].x += x0.x * e0.x + x0.y * e0.y;  ae[0].y += x0.y * e0.x - x0.x * e0.y;
        ae[1].x += x0.z * e0.x + x0.w * e0.y;  ae[1].y += x0.w * e0.x - x0.z * e0.y;
        ae[0].x += y0.x * e1.x + y0.y * e1.y;  ae[0].y += y0.y * e1.x - y0.x * e1.y;
        ae[1].x += y0.z * e1.x + y0.w * e1.y;  ae[1].y += y0.w * e1.x - y0.z * e1.y;
        // odd kx (diff operand)
        ao[0].x += x1.x * f0.x + x1.y * f0.y;  ao[0].y += x1.y * f0.x - x1.x * f0.y;
        ao[1].x += x1.z * f0.x + x1.w * f0.y;  ao[1].y += x1.w * f0.x - x1.z * f0.y;
        ao[0].x += y1.x * f1.x + y1.y * f1.y;  ao[0].y += y1.y * f1.x - y1.x * f1.y;
        ao[1].x += y1.z * f1.x + y1.w * f1.y;  ao[1].y += y1.w * f1.x - y1.z * f1.y;
    }
    int kyg = kh * 16 + kyl;
    float2* oe = g_XF + ((size_t)bc * 64 + kxe) * 32 + kyg;
    float2* oo = oe + 32;
    *(float4*)oe = make_float4(ae[0].x, ae[0].y, ae[1].x, ae[1].y);
    *(float4*)oo = make_float4(ao[0].x, ao[0].y, ao[1].x, ao[1].y);
}

// ---- per-mode complex channel mixing, ky-split for occupancy ----
__global__ void __launch_bounds__(512)
k_mix(const float* __restrict__ w1r, const float* __restrict__ w1i,
      const float* __restrict__ w2r, const float* __restrict__ w2i) {
    extern __shared__ char smraw[];
    float2* sXF = (float2*)smraw;   // [(b*64+i)*16 + kyl], 8192 float2 = 64KB
    int kxp   = blockIdx.x >> 2;
    int ohalf = (blockIdx.x >> 1) & 1;
    int kh    = blockIdx.x & 1;
    int tid = threadIdx.x;

    for (int i = tid; i < 8192; i += 512) {
        int b = i >> 10, rest = i & 1023, ii = rest >> 4, kk = rest & 15;
        sXF[i] = g_XF[(((size_t)b * PC + ii) * PKX + kxp) * PKY + kh * 16 + kk];
    }
    __syncthreads();

    int o   = ohalf * 32 + (tid >> 4);
    int kyl = tid & 15;
    int ky  = kh * 16 + kyl;
    const float* wr; const float* wi; int kxl;
    if (kxp < 32) { wr = w1r; wi = w1i; kxl = kxp; }
    else          { wr = w2r; wi = w2i; kxl = kxp - 32; }

    float ar[8], ai[8];
#pragma unroll
    for (int b = 0; b < 8; ++b) { ar[b] = 0.0f; ai[b] = 0.0f; }

    const float* wrp = wr + (size_t)o * 1024 + kxl * 32 + ky;
    const float* wip = wi + (size_t)o * 1024 + kxl * 32 + ky;
#pragma unroll 2
    for (int i = 0; i < 64; ++i) {
        float wrv = wrp[(size_t)i * 65536];
        float wiv = wip[(size_t)i * 65536];
#pragma unroll
        for (int b = 0; b < 8; ++b) {
            float2 v = sXF[(b * 64 + i) * 16 + kyl];
            ar[b] += v.x * wrv - v.y * wiv;
            ai[b] += v.x * wiv + v.y * wrv;
        }
    }
#pragma unroll
    for (int b = 0; b < 8; ++b)
        g_OF[(((size_t)b * PC + o) * PKX + kxp) * PKY + ky] = make_float2(ar[b], ai[b]);
}

// ---- inverse DFT along H, radix-2: Se/So over kx parity, emit h and h+128 ----
__global__ void __launch_bounds__(256) k_invH() {
    __shared__ float2 sOF[2048];
    __shared__ float2 ct[256];
    int tid = threadIdx.x, bc = blockIdx.x;

    const float4* src = (const float4*)(g_OF + (size_t)bc * 2048);
    float4* dst = (float4*)sOF;
    for (int i = tid; i < 1024; i += 256) dst[i] = src[i];
    ct[tid] = g_ct[tid];
    __syncthreads();

    int h0  = (tid >> 3) * 4;     // h<128
    int ky0 = (tid & 7) * 4;

    float2 ae[4][4], ao[4][4];
#pragma unroll
    for (int hh = 0; hh < 4; ++hh)
#pragma unroll
        for (int j = 0; j < 4; ++j) {
            ae[hh][j] = make_float2(0.f, 0.f);
            ao[hh][j] = make_float2(0.f, 0.f);
        }

    for (int kxp = 0; kxp < 64; kxp += 2) {
        int kxm = kxp + ((kxp >= 32) ? 192 : 0);   // even
        float2 te[4], to[4];
#pragma unroll
        for (int hh = 0; hh < 4; ++hh) {
            int h = h0 + hh;
            te[hh] = ct[(kxm * h) & 255];
            to[hh] = ct[((kxm + 1) * h) & 255];
        }
        float4 eA = *(const float4*)&sOF[kxp * 32 + ky0];
        float4 eB = *(const float4*)&sOF[kxp * 32 + ky0 + 2];
        float4 oA = *(const float4*)&sOF[(kxp + 1) * 32 + ky0];
        float4 oB = *(const float4*)&sOF[(kxp + 1) * 32 + ky0 + 2];
        float2 ove[4] = { {eA.x, eA.y}, {eA.z, eA.w}, {eB.x, eB.y}, {eB.z, eB.w} };
        float2 ovo[4] = { {oA.x, oA.y}, {oA.z, oA.w}, {oB.x, oB.y}, {oB.z, oB.w} };
#pragma unroll
        for (int hh = 0; hh < 4; ++hh) {
#pragma unroll
            for (int j = 0; j < 4; ++j) {
                ae[hh][j].x += ove[j].x * te[hh].x - ove[j].y * te[hh].y;
                ae[hh][j].y += ove[j].x * te[hh].y + ove[j].y * te[hh].x;
                ao[hh][j].x += ovo[j].x * to[hh].x - ovo[j].y * to[hh].y;
                ao[hh][j].y += ovo[j].x * to[hh].y + ovo[j].y * to[hh].x;
            }
        }
    }
#pragma unroll
    for (int j = 0; j < 4; ++j) {
        float2* out = g_Y1 + (size_t)bc * 8192 + (ky0 + j) * 256 + h0;
#pragma unroll
        for (int hh = 0; hh < 4; hh += 2) {
            *(float4*)&out[hh] = make_float4(
                ae[hh][j].x + ao[hh][j].x,     ae[hh][j].y + ao[hh][j].y,
                ae[hh+1][j].x + ao[hh+1][j].x, ae[hh+1][j].y + ao[hh+1][j].y);
            *(float4*)&out[hh + 128] = make_float4(
                ae[hh][j].x - ao[hh][j].x,     ae[hh][j].y - ao[hh][j].y,
                ae[hh+1][j].x - ao[hh+1][j].x, ae[hh+1][j].y - ao[hh+1][j].y);
        }
    }
}

// ---- inverse rfft along W, radix-2: Se/So over ky parity, emit w and w+128 ----
__global__ void __launch_bounds__(256) k_invW() {
    extern __shared__ char smraw[];
    float2* sY = (float2*)smraw;               // 8192 float2 (64KB)
    float2* sW = (float2*)(smraw + 65536);     // 31*32 float2
    __shared__ float rbuf[16];
    int tid = threadIdx.x;
    int bc = blockIdx.x >> 2, wt = blockIdx.x & 3;
    int w0 = wt * 32;

    const float4* src = (const float4*)(g_Y1 + (size_t)bc * 8192);
    float4* dst = (float4*)sY;
    for (int i = tid; i < 4096; i += 256) dst[i] = src[i];

    const float inv = 1.0f / 65536.0f;
    for (int i = tid; i < 31 * 32; i += 256) {
        int ky = (i >> 5) + 1;
        int w  = w0 + (i & 31);
        int idx = (ky * w) & 255;
        sW[i] = make_float2(2.0f * inv * g_cos[idx], 2.0f * inv * g_sin[idx]);
    }
    __syncthreads();

    int h0  = (tid >> 3) * 8;
    int wth = (tid & 7) * 4;

    float se[8][4], so[8][4], dc[8];
#pragma unroll
    for (int hh = 0; hh < 8; ++hh) {
        dc[hh] = inv * sY[h0 + hh].x;
#pragma unroll
        for (int ww = 0; ww < 4; ++ww) { se[hh][ww] = 0.f; so[hh][ww] = 0.f; }
    }

    for (int ky = 1; ky < 31; ky += 2) {
        {
            float2 av[8], bv[4];
            const float4* ap = (const float4*)&sY[ky * 256 + h0];
#pragma unroll
            for (int u = 0; u < 4; ++u) {
                float4 t1 = ap[u];
                av[2*u] = make_float2(t1.x, t1.y);
                av[2*u+1] = make_float2(t1.z, t1.w);
            }
            const float4* bp = (const float4*)&sW[(ky - 1) * 32 + wth];
            float4 t2 = bp[0], t3 = bp[1];
            bv[0] = make_float2(t2.x, t2.y); bv[1] = make_float2(t2.z, t2.w);
            bv[2] = make_float2(t3.x, t3.y); bv[3] = make_float2(t3.z, t3.w);
#pragma unroll
            for (int hh = 0; hh < 8; ++hh)
#pragma unroll
                for (int ww = 0; ww < 4; ++ww)
                    so[hh][ww] += av[hh].x * bv[ww].x - av[hh].y * bv[ww].y;
        }
        {
            float2 av[8], bv[4];
            const float4* ap = (const float4*)&sY[(ky + 1) * 256 + h0];
#pragma unroll
            for (int u = 0; u < 4; ++u) {
                float4 t1 = ap[u];
                av[2*u] = make_float2(t1.x, t1.y);
                av[2*u+1] = make_float2(t1.z, t1.w);
            }
            const float4* bp = (const float4*)&sW[ky * 32 + wth];
            float4 t2 = bp[0], t3 = bp[1];
            bv[0] = make_float2(t2.x, t2.y); bv[1] = make_float2(t2.z, t2.w);
            bv[2] = make_float2(t3.x, t3.y); bv[3] = make_float2(t3.z, t3.w);
#pragma unroll
            for (int hh = 0; hh < 8; ++hh)
#pragma unroll
                for (int ww = 0; ww < 4; ++ww)
                    se[hh][ww] += av[hh].x * bv[ww].x - av[hh].y * bv[ww].y;
        }
    }
    {
        float2 av[8], bv[4];
        const float4* ap = (const float4*)&sY[31 * 256 + h0];
#pragma unroll
        for (int u = 0; u < 4; ++u) {
            float4 t1 = ap[u];
            av[2*u] = make_float2(t1.x, t1.y);
            av[2*u+1] = make_float2(t1.z, t1.w);
        }
        const float4* bp = (const float4*)&sW[30 * 32 + wth];
        float4 t2 = bp[0], t3 = bp[1];
        bv[0] = make_float2(t2.x, t2.y); bv[1] = make_float2(t2.z, t2.w);
        bv[2] = make_float2(t3.x, t3.y); bv[3] = make_float2(t3.z, t3.w);
#pragma unroll
        for (int hh = 0; hh < 8; ++hh)
#pragma unroll
            for (int ww = 0; ww < 4; ++ww)
                so[hh][ww] += av[hh].x * bv[ww].x - av[hh].y * bv[ww].y;
    }

    float s = 0.0f, s2 = 0.0f;
#pragma unroll
    for (int hh = 0; hh < 8; ++hh) {
        float lo[4], hi[4];
#pragma unroll
        for (int ww = 0; ww < 4; ++ww) {
            lo[ww] = dc[hh] + se[hh][ww] + so[hh][ww];
            hi[ww] = dc[hh] + se[hh][ww] - so[hh][ww];
            s += lo[ww] + hi[ww];
            s2 += lo[ww] * lo[ww] + hi[ww] * hi[ww];
        }
        size_t base = (size_t)bc * 65536 + (size_t)(h0 + hh) * 256 + w0 + wth;
        *(float4*)&g_y[base]       = make_float4(lo[0], lo[1], lo[2], lo[3]);
        *(float4*)&g_y[base + 128] = make_float4(hi[0], hi[1], hi[2], hi[3]);
    }

    for (int off = 16; off > 0; off >>= 1) {
        s  += __shfl_down_sync(0xffffffffu, s,  off);
        s2 += __shfl_down_sync(0xffffffffu, s2, off);
    }
    int lane = tid & 31, wid = tid >> 5;
    if (lane == 0) { rbuf[wid] = s; rbuf[wid + 8] = s2; }
    __syncthreads();
    if (tid == 0) {
        float S = 0.0f, S2 = 0.0f;
        for (int i = 0; i < 8; ++i) { S += rbuf[i]; S2 += rbuf[i + 8]; }
        g_p1[blockIdx.x * 2] = S;
        g_p1[blockIdx.x * 2 + 1] = S2;
    }
}

__global__ void k_red1() {
    __shared__ float rbuf[16];
    int b = blockIdx.x, tid = threadIdx.x;
    float s  = g_p1[(b * 256 + tid) * 2];
    float s2 = g_p1[(b * 256 + tid) * 2 + 1];
    for (int off = 16; off > 0; off >>= 1) {
        s  += __shfl_down_sync(0xffffffffu, s,  off);
        s2 += __shfl_down_sync(0xffffffffu, s2, off);
    }
    int lane = tid & 31, wid = tid >> 5;
    if (lane == 0) { rbuf[wid] = s; rbuf[wid + 8] = s2; }
    __syncthreads();
    if (tid == 0) {
        float S = 0.0f, S2 = 0.0f;
        for (int i = 0; i < 8; ++i) { S += rbuf[i]; S2 += rbuf[i + 8]; }
        float mean = S * (1.0f / 4194304.0f);
        float var  = S2 * (1.0f / 4194304.0f) - mean * mean;
        g_s1[b * 2] = mean;
        g_s1[b * 2 + 1] = rsqrtf(var + 1e-5f);
    }
}

// ---- GN1 apply + residual + gelu + MLP + GN2 partials (W split in halves) ----
__global__ void __launch_bounds__(256) k_mlp(const float* __restrict__ x,
                      const float* __restrict__ nw, const float* __restrict__ nb,
                      const float* __restrict__ w1, const float* __restrict__ b1,
                      const float* __restrict__ w2, const float* __restrict__ b2) {
    extern __shared__ char smraw[];
    float* sy2  = (float*)smraw;        // [c][w]  64*128
    float* sh   = sy2 + 8192;           // [m][w]  32*128
    float* sw1  = sh + 4096;            // [c][m]  64*32
    float* sw2  = sw1 + 2048;           // [m][c]  32*64
    float* sb1  = sw2 + 2048;           // 32
    float* sb2v = sb1 + 32;             // 64
    float* snw  = sb2v + 64;            // 64
    float* snb  = snw + 64;             // 64
    __shared__ float rbuf[16];

    int tid = threadIdx.x;
    int b = blockIdx.x >> 8, h = blockIdx.x & 255;

    for (int i = tid; i < 2048; i += 256) {
        int c = i >> 5, m = i & 31;
        sw1[i] = w1[m * 64 + c];
        int m2 = i >> 6, c2 = i & 63;
        sw2[i] = w2[c2 * 32 + m2];
    }
    if (tid < 64) {
        sb2v[tid] = b2[tid];
        snw[tid] = nw[tid];
        snb[tid] = nb[tid];
        if (tid < 32) sb1[tid] = b1[tid];
    }
    float mean1 = g_s1[b * 2], rstd1 = g_s1[b * 2 + 1];
    __syncthreads();

    int m0 = (tid >> 5) * 4;
    int c0 = (tid >> 5) * 8;
    int wl = (tid & 31) * 4;

    float s = 0.0f, s2 = 0.0f;
    for (int half = 0; half < 2; ++half) {
        int wbase = half * 128;

        for (int i = tid; i < 2048; i += 256) {
            int c = i >> 5, w4 = (i & 31) * 4;
            size_t gid = (size_t)(b * 64 + c) * 65536 + (size_t)h * 256 + wbase + w4;
            float4 yv = *(const float4*)&g_y[gid];
            float4 xv = *(const float4*)&x[gid];
            float a = snw[c] * rstd1, bb = snb[c] - mean1 * rstd1 * snw[c];
            float4 o;
            o.x = gelu_f(yv.x * a + bb + xv.x);
            o.y = gelu_f(yv.y * a + bb + xv.y);
            o.z = gelu_f(yv.z * a + bb + xv.z);
            o.w = gelu_f(yv.w * a + bb + xv.w);
            *(float4*)&sy2[c * 128 + w4] = o;
        }
        __syncthreads();

        {
            float acc[4][4];
#pragma unroll
            for (int mm = 0; mm < 4; ++mm)
#pragma unroll
                for (int ww = 0; ww < 4; ++ww) acc[mm][ww] = 0.0f;
            for (int c = 0; c < 64; ++c) {
                float4 wv = *(const float4*)&sw1[c * 32 + m0];
                float4 yv = *(const float4*)&sy2[c * 128 + wl];
                float wa[4] = { wv.x, wv.y, wv.z, wv.w };
                float yy[4] = { yv.x, yv.y, yv.z, yv.w };
#pragma unroll
                for (int mm = 0; mm < 4; ++mm)
#pragma unroll
                    for (int ww = 0; ww < 4; ++ww) acc[mm][ww] += wa[mm] * yy[ww];
            }
#pragma unroll
            for (int mm = 0; mm < 4; ++mm) {
                float bb = sb1[m0 + mm];
                float4 o;
                o.x = gelu_f(acc[mm][0] + bb);
                o.y = gelu_f(acc[mm][1] + bb);
                o.z = gelu_f(acc[mm][2] + bb);
                o.w = gelu_f(acc[mm][3] + bb);
                *(float4*)&sh[(m0 + mm) * 128 + wl] = o;
            }
        }
        __syncthreads();

        {
            float acc2[8][4];
#pragma unroll
            for (int cc = 0; cc < 8; ++cc)
#pragma unroll
                for (int ww = 0; ww < 4; ++ww) acc2[cc][ww] = 0.0f;
            for (int m = 0; m < 32; ++m) {
                float4 a0 = *(const float4*)&sw2[m * 64 + c0];
                float4 a1 = *(const float4*)&sw2[m * 64 + c0 + 4];
                float4 hv = *(const float4*)&sh[m * 128 + wl];
                float wa[8] = { a0.x, a0.y, a0.z, a0.w, a1.x, a1.y, a1.z, a1.w };
                float hh[4] = { hv.x, hv.y, hv.z, hv.w };
#pragma unroll
                for (int cc = 0; cc < 8; ++cc)
#pragma unroll
                    for (int ww = 0; ww < 4; ++ww) acc2[cc][ww] += wa[cc] * hh[ww];
            }
#pragma unroll
            for (int cc = 0; cc < 8; ++cc) {
                float bb = sb2v[c0 + cc];
                float o[4];
#pragma unroll
                for (int ww = 0; ww < 4; ++ww) {
                    o[ww] = acc2[cc][ww] + bb;
                    s += o[ww];
                    s2 += o[ww] * o[ww];
                }
                size_t gbase = (size_t)(b * 64 + c0 + cc) * 65536 + (size_t)h * 256 + wbase;
                *(float4*)&g_z[gbase + wl] = make_float4(o[0], o[1], o[2], o[3]);
            }
        }
        __syncthreads();
    }

    for (int off = 16; off > 0; off >>= 1) {
        s  += __shfl_down_sync(0xffffffffu, s,  off);
        s2 += __shfl_down_sync(0xffffffffu, s2, off);
    }
    int lane = tid & 31, widx = tid >> 5;
    if (lane == 0) { rbuf[widx] = s; rbuf[widx + 8] = s2; }
    __syncthreads();
    if (tid == 0) {
        float S = 0.0f, S2 = 0.0f;
        for (int i = 0; i < 8; ++i) { S += rbuf[i]; S2 += rbuf[i + 8]; }
        g_p2[blockIdx.x * 2] = S;
        g_p2[blockIdx.x * 2 + 1] = S2;
    }
}

__global__ void k_red2() {
    __shared__ float rbuf[16];
    int b = blockIdx.x, tid = threadIdx.x;
    float s  = g_p2[(b * 256 + tid) * 2];
    float s2 = g_p2[(b * 256 + tid) * 2 + 1];
    for (int off = 16; off > 0; off >>= 1) {
        s  += __shfl_down_sync(0xffffffffu, s,  off);
        s2 += __shfl_down_sync(0xffffffffu, s2, off);
    }
    int lane = tid & 31, wid = tid >> 5;
    if (lane == 0) { rbuf[wid] = s; rbuf[wid + 8] = s2; }
    __syncthreads();
    if (tid == 0) {
        float S = 0.0f, S2 = 0.0f;
        for (int i = 0; i < 8; ++i) { S += rbuf[i]; S2 += rbuf[i + 8]; }
        float mean = S * (1.0f / 4194304.0f);
        float var  = S2 * (1.0f / 4194304.0f) - mean * mean;
        g_s2[b * 2] = mean;
        g_s2[b * 2 + 1] = rsqrtf(var + 1e-5f);
    }
}

// ---- final: FiLM GN + skip2 ----
__global__ void k_final(const float* __restrict__ x, float* __restrict__ out) {
    int gi = blockIdx.x * 256 + threadIdx.x;
#pragma unroll
    for (int u = 0; u < 4; ++u) {
        size_t i4 = (size_t)gi + (size_t)u * 2097152;
        size_t e = i4 * 4;
        int b = (int)(e >> 22);
        int c = (int)((e >> 16) & 63);
        float mean = g_s2[b * 2], rstd = g_s2[b * 2 + 1];
        float ga = g_gb[(b * 64 + c) * 2], be = g_gb[(b * 64 + c) * 2 + 1];
        float4 zv = ((const float4*)g_z)[i4];
        float4 xv = ((const float4*)x)[i4];
        float4 ov;
        ov.x = ga * (zv.x - mean) * rstd + be + gelu_f(xv.x);
        ov.y = ga * (zv.y - mean) * rstd + be + gelu_f(xv.y);
        ov.z = ga * (zv.z - mean) * rstd + be + gelu_f(xv.z);
        ov.w = ga * (zv.w - mean) * rstd + be + gelu_f(xv.w);
        ((float4*)out)[i4] = ov;
    }
}

extern "C" void kernel_launch(void* const* d_in, const int* in_sizes, int n_in,
                              void* d_out, int out_size) {
    const float* x       = (const float*)d_in[0];
    const float* t       = (const float*)d_in[1];
    const float* w1r     = (const float*)d_in[2];
    const float* w1i     = (const float*)d_in[3];
    const float* w2r     = (const float*)d_in[4];
    const float* w2i     = (const float*)d_in[5];
    const float* norm1_w = (const float*)d_in[6];
    const float* norm1_b = (const float*)d_in[7];
    const float* mlp_w1  = (const float*)d_in[8];
    const float* mlp_b1  = (const float*)d_in[9];
    const float* mlp_w2  = (const float*)d_in[10];
    const float* mlp_b2  = (const float*)d_in[11];
    const float* gamma_w = (const float*)d_in[12];
    const float* gamma_b = (const float*)d_in[13];
    const float* beta_w  = (const float*)d_in[14];
    const float* beta_b  = (const float*)d_in[15];
    float* out = (float*)d_out;

    cudaFuncSetAttribute(k_fwdW, cudaFuncAttributeMaxDynamicSharedMemorySize, 98304);
    cudaFuncSetAttribute(k_fwdH, cudaFuncAttributeMaxDynamicSharedMemorySize, 34816);
    cudaFuncSetAttribute(k_mix,  cudaFuncAttributeMaxDynamicSharedMemorySize, 65536);
    cudaFuncSetAttribute(k_invW, cudaFuncAttributeMaxDynamicSharedMemorySize, 73728);
    cudaFuncSetAttribute(k_mlp,  cudaFuncAttributeMaxDynamicSharedMemorySize, 66432);

    k_tab<<<1, 256>>>();
    k_film<<<PB, PC>>>(t, gamma_w, gamma_b, beta_w, beta_b);
    k_fwdW<<<NROWS / 64, 256, 98304>>>(x);
    k_fwdH<<<PB * PC * 2, 256, 34816>>>();
    k_mix<<<256, 512, 65536>>>(w1r, w1i, w2r, w2i);
    k_invH<<<PB * PC, 256>>>();
    k_invW<<<PB * PC * 4, 256, 73728>>>();
    k_red1<<<PB, 256>>>();
    k_mlp<<<PB * PH, 256, 66432>>>(x, norm1_w, norm1_b,
                                   mlp_w1, mlp_b1, mlp_w2, mlp_b2);
    k_red2<<<PB, 256>>>();
    k_final<<<8192, 256>>>(x, out);
}